// round 10
// baseline (speedup 1.0000x reference)
#include <cuda_runtime.h>
#include <cstdint>

#define T_STEPS 2048
#define HV 32
#define HKC 16
#define DHEAD 64
#define CONV_DIM_C 4096
#define KEY_DIM_C 1024
#define NCHUNK 32
#define SP 68          // smem row stride (floats), 16B-aligned

// ---- scratch (static __device__, no allocation) ----
__device__ float g_qn[T_STEPS * HKC * DHEAD];
__device__ float g_kn[T_STEPS * HKC * DHEAD];
__device__ float g_v [T_STEPS * HV * DHEAD];
__device__ float g_g   [T_STEPS * HV];
__device__ float g_beta[T_STEPS * HV];
__device__ float g_Qeff[NCHUNK * HV * 4096];
__device__ float g_G   [NCHUNK * HV * 4096];
__device__ float g_H   [NCHUNK * HV * 4096];
__device__ float g_ST  [NCHUNK * HV * 4096];   // chunk-start states, [v][k]

// ---- f32x2 packed FMA helpers ----
__device__ __forceinline__ void ffma2(unsigned long long& acc,
                                      unsigned long long a, unsigned long long b) {
    asm("fma.rn.f32x2 %0, %1, %2, %0;" : "+l"(acc) : "l"(a), "l"(b));
}
__device__ __forceinline__ float hsum(unsigned long long u) {
    float2 f = *reinterpret_cast<float2*>(&u);
    return f.x + f.y;
}

// ---- cp.async helpers ----
__device__ __forceinline__ void cp_async16(void* dst, const void* src) {
    uint32_t d = (uint32_t)__cvta_generic_to_shared(dst);
    asm volatile("cp.async.cg.shared.global [%0], [%1], 16;" :: "r"(d), "l"(src));
}
__device__ __forceinline__ void cp_commit() {
    asm volatile("cp.async.commit_group;");
}
__device__ __forceinline__ void cp_wait0() {
    asm volatile("cp.async.wait_group 0;");
}

// Single-X matmul: Z[r][c] = sum_d X[r][d]*YT[c][d]
__device__ __forceinline__ void mm64x(const float* __restrict__ X,
                                      const float* __restrict__ YT,
                                      int r0, int tx, unsigned long long* __restrict__ acc)
{
#pragma unroll 4
    for (int d = 0; d < 64; d += 4) {
        ulonglong2 x0 = *(const ulonglong2*)(X + (r0 + 0) * SP + d);
        ulonglong2 x1 = *(const ulonglong2*)(X + (r0 + 1) * SP + d);
        ulonglong2 x2 = *(const ulonglong2*)(X + (r0 + 2) * SP + d);
        ulonglong2 x3 = *(const ulonglong2*)(X + (r0 + 3) * SP + d);
        ulonglong2 y0 = *(const ulonglong2*)(YT + (tx +  0) * SP + d);
        ulonglong2 y1 = *(const ulonglong2*)(YT + (tx + 16) * SP + d);
        ulonglong2 y2 = *(const ulonglong2*)(YT + (tx + 32) * SP + d);
        ulonglong2 y3 = *(const ulonglong2*)(YT + (tx + 48) * SP + d);
        ffma2(acc[ 0], x0.x, y0.x); ffma2(acc[ 0], x0.y, y0.y);
        ffma2(acc[ 1], x0.x, y1.x); ffma2(acc[ 1], x0.y, y1.y);
        ffma2(acc[ 2], x0.x, y2.x); ffma2(acc[ 2], x0.y, y2.y);
        ffma2(acc[ 3], x0.x, y3.x); ffma2(acc[ 3], x0.y, y3.y);
        ffma2(acc[ 4], x1.x, y0.x); ffma2(acc[ 4], x1.y, y0.y);
        ffma2(acc[ 5], x1.x, y1.x); ffma2(acc[ 5], x1.y, y1.y);
        ffma2(acc[ 6], x1.x, y2.x); ffma2(acc[ 6], x1.y, y2.y);
        ffma2(acc[ 7], x1.x, y3.x); ffma2(acc[ 7], x1.y, y3.y);
        ffma2(acc[ 8], x2.x, y0.x); ffma2(acc[ 8], x2.y, y0.y);
        ffma2(acc[ 9], x2.x, y1.x); ffma2(acc[ 9], x2.y, y1.y);
        ffma2(acc[10], x2.x, y2.x); ffma2(acc[10], x2.y, y2.y);
        ffma2(acc[11], x2.x, y3.x); ffma2(acc[11], x2.y, y3.y);
        ffma2(acc[12], x3.x, y0.x); ffma2(acc[12], x3.y, y0.y);
        ffma2(acc[13], x3.x, y1.x); ffma2(acc[13], x3.y, y1.y);
        ffma2(acc[14], x3.x, y2.x); ffma2(acc[14], x3.y, y2.y);
        ffma2(acc[15], x3.x, y3.x); ffma2(acc[15], x3.y, y3.y);
    }
}

// ---------------------------------------------------------------------------
// Kernel 1: conv1d(W=4)+silu+split+l2norm. 4 time-rows per CTA.
// ---------------------------------------------------------------------------
__global__ __launch_bounds__(256) void conv_kernel(
    const float* __restrict__ x,
    const float* __restrict__ cstate,
    const float* __restrict__ wgt)
{
    const int t0 = blockIdx.y * 4;
    const int c  = blockIdx.x * 1024 + threadIdx.x * 4;

    float4 w[4];
#pragma unroll
    for (int j = 0; j < 4; j++) w[j] = *(const float4*)(wgt + (size_t)(c + j) * 4);

    float4 xr[7];
#pragma unroll
    for (int rr = 0; rr < 7; rr++) {
        int r = t0 - 3 + rr;
        xr[rr] = (r >= 0) ? *(const float4*)(x + (size_t)r * CONV_DIM_C + c)
                          : *(const float4*)(cstate + (size_t)(r + 3) * CONV_DIM_C + c);
    }

    float acc[4][4];
#pragma unroll
    for (int tt = 0; tt < 4; tt++) {
        float xv0[4] = {xr[tt].x, xr[tt].y, xr[tt].z, xr[tt].w};
        float xv1[4] = {xr[tt+1].x, xr[tt+1].y, xr[tt+1].z, xr[tt+1].w};
        float xv2[4] = {xr[tt+2].x, xr[tt+2].y, xr[tt+2].z, xr[tt+2].w};
        float xv3[4] = {xr[tt+3].x, xr[tt+3].y, xr[tt+3].z, xr[tt+3].w};
#pragma unroll
        for (int j = 0; j < 4; j++) {
            float s = xv0[j] * w[j].x;
            s = fmaf(xv1[j], w[j].y, s);
            s = fmaf(xv2[j], w[j].z, s);
            s = fmaf(xv3[j], w[j].w, s);
            acc[tt][j] = s / (1.f + __expf(-s));
        }
    }

    if (c < 2 * KEY_DIM_C) {
        float ss[4];
#pragma unroll
        for (int tt = 0; tt < 4; tt++) {
            float s = 0.f;
#pragma unroll
            for (int j = 0; j < 4; j++) s = fmaf(acc[tt][j], acc[tt][j], s);
            s += __shfl_xor_sync(0xffffffffu, s, 1);
            s += __shfl_xor_sync(0xffffffffu, s, 2);
            s += __shfl_xor_sync(0xffffffffu, s, 4);
            s += __shfl_xor_sync(0xffffffffu, s, 8);
            ss[tt] = rsqrtf(s + 1e-6f);
        }
        const bool isq = (c < KEY_DIM_C);
#pragma unroll
        for (int tt = 0; tt < 4; tt++) {
            float sc = isq ? ss[tt] * 0.125f : ss[tt];
            float* dst = isq ? (g_qn + (size_t)(t0 + tt) * 1024 + c)
                             : (g_kn + (size_t)(t0 + tt) * 1024 + (c - KEY_DIM_C));
            *(float4*)dst = make_float4(acc[tt][0]*sc, acc[tt][1]*sc, acc[tt][2]*sc, acc[tt][3]*sc);
        }
    } else {
#pragma unroll
        for (int tt = 0; tt < 4; tt++) {
            float* dst = g_v + (size_t)(t0 + tt) * 2048 + (c - 2048);
            *(float4*)dst = make_float4(acc[tt][0], acc[tt][1], acc[tt][2], acc[tt][3]);
        }
    }
}

// ---------------------------------------------------------------------------
// Kernel 2: gates
// ---------------------------------------------------------------------------
__global__ void gates_kernel(
    const float* __restrict__ b, const float* __restrict__ a,
    const float* __restrict__ alog, const float* __restrict__ dtb)
{
    int i = blockIdx.x * blockDim.x + threadIdx.x;
    if (i >= T_STEPS * HV) return;
    int h = i & 31;
    g_beta[i] = 1.f / (1.f + expf(-b[i]));
    float xx = a[i] + dtb[h];
    float sp = (xx > 20.f) ? xx : log1pf(expf(xx));
    g_g[i] = -expf(alog[h]) * sp;
}

// ---------------------------------------------------------------------------
// Kernel 3: per-chunk WY-form precompute. 1024 CTAs, 256 threads, 2 CTA/SM
// (smem-limited). The six 64^3 matmuls run from TWO rolled pass-loops so the
// mm body exists twice in SASS (small I-footprint), not six times.
// ---------------------------------------------------------------------------
__global__ __launch_bounds__(256) void chunk_kernel(float* __restrict__ out)
{
    extern __shared__ float sm[];
    float* sK   = sm;                 // [64][SP] K row-major, then Attn
    float* sKT  = sK  + 64 * SP;      // [64][SP] K^T (later Cbar^T)
    float* sQr  = sKT + 64 * SP;      // [64][SP] q normalized+scaled
    float* sM   = sQr + 64 * SP;      // [64][SP] M (solve matrix) -> W^T
    float* sW   = sM  + 64 * SP;      // [64][SP] W rhs/solved [t][k] -> P^T
    float* sP   = sW  + 64 * SP;      // [64][SP] beta*V / P [t][v]
    float* scg  = sP  + 64 * SP;      // [64]
    float* sE   = scg  + 64;
    float* sBeta= sE   + 64;
    float* sBE  = sBeta+ 64;
    float* sTmp = sBE  + 64;

    const int cid = blockIdx.x;
    const int i = cid >> 5;
    const int h = cid & 31;
    const int tid = threadIdx.x;
    const int ty = tid >> 4, tx = tid & 15;
    const int r0 = ty * 4;

    // ---- load K (+transpose), Q, V (row-major) ----
    const float* Kg = g_kn + (size_t)(i * 64) * 1024 + (h >> 1) * 64;
    const float* Qg = g_qn + (size_t)(i * 64) * 1024 + (h >> 1) * 64;
    const float* Vg = g_v  + (size_t)(i * 64) * 2048 + h * 64;
    for (int idx = tid; idx < 64 * 16; idx += 256) {
        int r = idx >> 4, c4 = (idx & 15) << 2;
        float4 kv = *(const float4*)(Kg + (size_t)r * 1024 + c4);
        sK[r * SP + c4 + 0] = kv.x; sK[r * SP + c4 + 1] = kv.y;
        sK[r * SP + c4 + 2] = kv.z; sK[r * SP + c4 + 3] = kv.w;
        sKT[(c4 + 0) * SP + r] = kv.x; sKT[(c4 + 1) * SP + r] = kv.y;
        sKT[(c4 + 2) * SP + r] = kv.z; sKT[(c4 + 3) * SP + r] = kv.w;
        float4 qv = *(const float4*)(Qg + (size_t)r * 1024 + c4);
        sQr[r * SP + c4 + 0] = qv.x; sQr[r * SP + c4 + 1] = qv.y;
        sQr[r * SP + c4 + 2] = qv.z; sQr[r * SP + c4 + 3] = qv.w;
        float4 vv = *(const float4*)(Vg + (size_t)r * 2048 + c4);
        *(float4*)(sP + r * SP + c4) = vv;
    }
    if (tid < 64) {
        scg[tid]   = g_g   [(size_t)(i * 64 + tid) * 32 + h];
        sBeta[tid] = g_beta[(size_t)(i * 64 + tid) * 32 + h];
    }
    __syncthreads();

    // ---- inclusive scan of log-decay ----
#pragma unroll
    for (int off = 1; off < 64; off <<= 1) {
        float v = 0.f;
        if (tid < 64) v = scg[tid] + ((tid >= off) ? scg[tid - off] : 0.f);
        __syncthreads();
        if (tid < 64) scg[tid] = v;
        __syncthreads();
    }
    if (tid < 64) {
        float e = __expf(scg[tid]);
        sE[tid] = e;
        sBE[tid] = e * sBeta[tid];
        sTmp[tid] = __expf(scg[63] - scg[tid]);
    }
    __syncthreads();

    // ---- RHS init (row-major): sW[t][k] = BE[t]*K[t][k]; sP[t][v] *= beta[t]
    for (int idx = tid; idx < 1024; idx += 256) {
        int r = idx >> 4, c4 = (idx & 15) << 2;
        float be = sBE[r], bb = sBeta[r];
        float4 kv = *(const float4*)(sK + r * SP + c4);
        *(float4*)(sW + r * SP + c4) =
            make_float4(be * kv.x, be * kv.y, be * kv.z, be * kv.w);
        float4 pv = *(const float4*)(sP + r * SP + c4);
        *(float4*)(sP + r * SP + c4) =
            make_float4(bb * pv.x, bb * pv.y, bb * pv.z, bb * pv.w);
    }
    __syncthreads();

    // ---- phase 1 (rolled): pass 0: X=K -> M;  pass 1: X=Q -> Attn (into sK)
#pragma unroll 1
    for (int pass = 0; pass < 2; pass++) {
        unsigned long long acc[16];
#pragma unroll
        for (int j = 0; j < 16; j++) acc[j] = 0ull;
        mm64x(pass ? sQr : sK, sK, r0, tx, acc);
        __syncthreads();   // pass 1: all sK reads complete before overwrite
        if (pass == 0) {
#pragma unroll
            for (int ri = 0; ri < 4; ri++) {
                int t = r0 + ri;
                float bt = sBeta[t], ct = scg[t];
#pragma unroll
                for (int ci = 0; ci < 4; ci++) {
                    int s = tx + 16 * ci;
                    sM[t * SP + s] =
                        (s < t) ? bt * hsum(acc[ri * 4 + ci]) * __expf(ct - scg[s]) : 0.f;
                }
            }
        } else {
#pragma unroll
            for (int ri = 0; ri < 4; ri++) {
                int t = r0 + ri;
                float ct = scg[t];
#pragma unroll
                for (int ci = 0; ci < 4; ci++) {
                    int s = tx + 16 * ci;
                    sK[t * SP + s] =
                        (s <= t) ? hsum(acc[ri * 4 + ci]) * __expf(ct - scg[s]) : 0.f;
                }
            }
        }
        __syncthreads();
    }

    // ---- solve (I+M)X = RHS, row-major layout: X[t][cc], lane-contiguous ----
    if (tid < 128) {
        float* X = (tid < 64) ? sW : sP;
        const int cc = tid & 63;
        for (int t = 0; t < 64; t++) {
            float r = X[t * SP + cc];
            const float* Mr = sM + t * SP;
            float b0 = 0.f, b1 = 0.f, b2 = 0.f, b3 = 0.f;
            int s = 0;
            for (; s + 4 <= t; s += 4) {
                b0 = fmaf(Mr[s + 0], X[(s + 0) * SP + cc], b0);
                b1 = fmaf(Mr[s + 1], X[(s + 1) * SP + cc], b1);
                b2 = fmaf(Mr[s + 2], X[(s + 2) * SP + cc], b2);
                b3 = fmaf(Mr[s + 3], X[(s + 3) * SP + cc], b3);
            }
            for (; s < t; s++) b0 = fmaf(Mr[s], X[s * SP + cc], b0);
            X[t * SP + cc] = r - ((b0 + b1) + (b2 + b3));
        }
    }
    __syncthreads();

    // ---- transpose W: sW[t][k] -> sM[k][t]; scale sKT -> Cbar^T ----
    for (int idx = tid; idx < 1024; idx += 256) {
        int r = idx >> 4, c4 = (idx & 15) << 2;
        float4 w = *(const float4*)(sW + r * SP + c4);
        sM[(c4 + 0) * SP + r] = w.x; sM[(c4 + 1) * SP + r] = w.y;
        sM[(c4 + 2) * SP + r] = w.z; sM[(c4 + 3) * SP + r] = w.w;
    }
    for (int idx = tid; idx < 4096; idx += 256) {
        int r = idx >> 6, s = idx & 63;
        sKT[r * SP + s] *= sTmp[s];
    }
    __syncthreads();

    // ---- transpose P: sP[t][v] -> sW[v][t] ----
    for (int idx = tid; idx < 1024; idx += 256) {
        int r = idx >> 4, c4 = (idx & 15) << 2;
        float4 p = *(const float4*)(sP + r * SP + c4);
        sW[(c4 + 0) * SP + r] = p.x; sW[(c4 + 1) * SP + r] = p.y;
        sW[(c4 + 2) * SP + r] = p.z; sW[(c4 + 3) * SP + r] = p.w;
    }
    __syncthreads();

    const size_t base = ((size_t)(i * 32 + h)) << 12;

    // ---- phase 2 (rolled): 4 matmuls, all outputs to global ----
    //   pass 0: Attn  @ W^T -> Qeff      pass 1: Cbar^T @ W^T -> G
    //   pass 2: Attn  @ P^T -> Ointra    pass 3: Cbar^T @ P^T -> H
#pragma unroll 1
    for (int pass = 0; pass < 4; pass++) {
        const float* X = (pass & 1) ? sKT : sK;
        const float* Y = (pass < 2) ? sM : sW;
        unsigned long long acc[16];
#pragma unroll
        for (int j = 0; j < 16; j++) acc[j] = 0ull;
        mm64x(X, Y, r0, tx, acc);
        if (pass == 0) {
#pragma unroll
            for (int ri = 0; ri < 4; ri++) {
                int t = r0 + ri;
                float et = sE[t];
#pragma unroll
                for (int ci = 0; ci < 4; ci++) {
                    int s = tx + 16 * ci;
                    g_Qeff[base + t * 64 + s] =
                        fmaf(et, sQr[t * SP + s], -hsum(acc[ri * 4 + ci]));
                }
            }
        } else if (pass == 1) {
            float b63 = sE[63];
#pragma unroll
            for (int ri = 0; ri < 4; ri++) {
                int t = r0 + ri;
#pragma unroll
                for (int ci = 0; ci < 4; ci++) {
                    int s = tx + 16 * ci;
                    g_G[base + t * 64 + s] =
                        ((t == s) ? b63 : 0.f) - hsum(acc[ri * 4 + ci]);
                }
            }
        } else if (pass == 2) {
#pragma unroll
            for (int ri = 0; ri < 4; ri++) {
                int t = r0 + ri;
                float* op = out + (size_t)(i * 64 + t) * 2048 + h * 64;
#pragma unroll
                for (int ci = 0; ci < 4; ci++)
                    op[tx + 16 * ci] = hsum(acc[ri * 4 + ci]);
            }
        } else {
#pragma unroll
            for (int ri = 0; ri < 4; ri++) {
                int t = r0 + ri;
#pragma unroll
                for (int ci = 0; ci < 4; ci++) {
                    int s = tx + 16 * ci;
                    g_H[base + t * 64 + s] = hsum(acc[ri * 4 + ci]);
                }
            }
        }
    }
}

// ---------------------------------------------------------------------------
// Kernel 4: state pass (R7 proven, 63.5us). 64 CTAs = (head, v-half) x 256.
// ---------------------------------------------------------------------------
__global__ __launch_bounds__(256) void state_kernel(const float* __restrict__ S0)
{
    extern __shared__ float sms[];
    float* sG0 = sms;                 // [64][SP]
    float* sG1 = sG0 + 64 * SP;
    float* sS0 = sG1 + 64 * SP;       // [32 v][SP] (k contiguous)
    float* sS1 = sS0 + 32 * SP;

    const int h = blockIdx.x >> 1;
    const int vbase = (blockIdx.x & 1) * 32;
    const int tid = threadIdx.x;
    const int wrp = tid >> 5, l = tid & 31;
    const int k0 = wrp * 8;
    const int vloc = l;
    const int vglob = vbase + vloc;

    const size_t hbase = ((size_t)h) << 12;

    for (int idx = tid; idx < 2048; idx += 256) {
        int k = idx >> 5, v = idx & 31;
        sS0[v * SP + k] = S0[hbase + k * 64 + vbase + v];
    }
#pragma unroll
    for (int j = 0; j < 4; j++) {
        int seg = tid + j * 256;
        int r = seg >> 4, c4 = (seg & 15) << 2;
        cp_async16(sG0 + r * SP + c4, g_G + hbase + r * 64 + c4);
    }
    cp_commit();
    float hcur[8];
#pragma unroll
    for (int r = 0; r < 8; r++)
        hcur[r] = g_H[hbase + (k0 + r) * 64 + vglob];
    cp_wait0();
    __syncthreads();

    float* Scur = sS0; float* Snxt = sS1;
    float* Gcur = sG0; float* Gnxt = sG1;

    for (int i = 0; i < NCHUNK; i++) {
        const size_t basei = ((size_t)(i * 32 + h)) << 12;
        for (int idx = tid; idx < 512; idx += 256) {
            int v = idx >> 4, k4 = (idx & 15) << 2;
            *(float4*)(g_ST + basei + (vbase + v) * 64 + k4) =
                *(const float4*)(Scur + v * SP + k4);
        }
        if (i == NCHUNK - 1) break;

        const size_t basen = ((size_t)((i + 1) * 32 + h)) << 12;
#pragma unroll
        for (int j = 0; j < 4; j++) {
            int seg = tid + j * 256;
            int r = seg >> 4, c4 = (seg & 15) << 2;
            cp_async16(Gnxt + r * SP + c4, g_G + basen + r * 64 + c4);
        }
        cp_commit();
        float hpre[8];
#pragma unroll
        for (int r = 0; r < 8; r++)
            hpre[r] = g_H[basen + (k0 + r) * 64 + vglob];

        unsigned long long acc[8];
#pragma unroll
        for (int j = 0; j < 8; j++) acc[j] = 0ull;
#pragma unroll 4
        for (int d = 0; d < 64; d += 4) {
            ulonglong2 y = *(const ulonglong2*)(Scur + vloc * SP + d);
#pragma unroll
            for (int r = 0; r < 8; r++) {
                ulonglong2 x = *(const ulonglong2*)(Gcur + (k0 + r) * SP + d);
                ffma2(acc[r], x.x, y.x); ffma2(acc[r], x.y, y.y);
            }
        }
        {
            float4 o0, o1;
            o0.x = hsum(acc[0]) + hcur[0]; o0.y = hsum(acc[1]) + hcur[1];
            o0.z = hsum(acc[2]) + hcur[2]; o0.w = hsum(acc[3]) + hcur[3];
            o1.x = hsum(acc[4]) + hcur[4]; o1.y = hsum(acc[5]) + hcur[5];
            o1.z = hsum(acc[6]) + hcur[6]; o1.w = hsum(acc[7]) + hcur[7];
            *(float4*)(Snxt + vloc * SP + k0)     = o0;
            *(float4*)(Snxt + vloc * SP + k0 + 4) = o1;
        }
#pragma unroll
        for (int j = 0; j < 8; j++) hcur[j] = hpre[j];
        cp_wait0();
        __syncthreads();
        float* t1 = Scur; Scur = Snxt; Snxt = t1;
        float* t2 = Gcur; Gcur = Gnxt; Gnxt = t2;
    }
}

// ---------------------------------------------------------------------------
// Kernel 5: O pass (fully parallel). out += Qeff_i @ S_i. 1024 CTAs.
// ---------------------------------------------------------------------------
__global__ __launch_bounds__(256) void opass_kernel(float* __restrict__ out)
{
    __shared__ float sQe[64 * SP];
    __shared__ float sST[64 * SP];

    const int bi = blockIdx.x;
    const int i = bi >> 5;
    const int h = bi & 31;
    const int tid = threadIdx.x;
    const int ty = tid >> 4, tx = tid & 15;
    const int r0 = ty * 4;

    const size_t base = ((size_t)(i * 32 + h)) << 12;
    for (int idx = tid; idx < 1024; idx += 256) {
        int r = idx >> 4, c4 = (idx & 15) << 2;
        float4 q = *(const float4*)(g_Qeff + base + r * 64 + c4);
        sQe[r * SP + c4 + 0] = q.x; sQe[r * SP + c4 + 1] = q.y;
        sQe[r * SP + c4 + 2] = q.z; sQe[r * SP + c4 + 3] = q.w;
        float4 s = *(const float4*)(g_ST + base + r * 64 + c4);
        sST[r * SP + c4 + 0] = s.x; sST[r * SP + c4 + 1] = s.y;
        sST[r * SP + c4 + 2] = s.z; sST[r * SP + c4 + 3] = s.w;
    }
    __syncthreads();

    unsigned long long acc[16];
#pragma unroll
    for (int j = 0; j < 16; j++) acc[j] = 0ull;
    mm64x(sQe, sST, r0, tx, acc);

#pragma unroll
    for (int ri = 0; ri < 4; ri++) {
        int t = r0 + ri;
        float* op = out + (size_t)(i * 64 + t) * 2048 + h * 64;
#pragma unroll
        for (int ci = 0; ci < 4; ci++) {
            int s = tx + 16 * ci;
            op[s] += hsum(acc[ri * 4 + ci]);
        }
    }
}

// ---------------------------------------------------------------------------
extern "C" void kernel_launch(void* const* d_in, const int* in_sizes, int n_in,
                              void* d_out, int out_size)
{
    const float* x    = (const float*)d_in[0];
    const float* cs   = (const float*)d_in[1];
    const float* s0   = (const float*)d_in[2];
    const float* b    = (const float*)d_in[3];
    const float* a    = (const float*)d_in[4];
    const float* w    = (const float*)d_in[5];
    const float* alog = (const float*)d_in[6];
    const float* dtb  = (const float*)d_in[7];

    const int chunk_smem = (6 * 64 * SP + 5 * 64) * sizeof(float);      // ~105.7 KB
    const int state_smem = (2 * 64 * SP + 2 * 32 * SP) * sizeof(float); // ~52.2 KB
    static bool attr_done = false;
    if (!attr_done) {
        cudaFuncSetAttribute(chunk_kernel,
                             cudaFuncAttributeMaxDynamicSharedMemorySize, chunk_smem);
        cudaFuncSetAttribute(state_kernel,
                             cudaFuncAttributeMaxDynamicSharedMemorySize, state_smem);
        attr_done = true;
    }

    conv_kernel<<<dim3(4, T_STEPS / 4), 256>>>(x, cs, w);
    gates_kernel<<<(T_STEPS * HV + 255) / 256, 256>>>(b, a, alog, dtb);
    chunk_kernel<<<NCHUNK * HV, 256, chunk_smem>>>((float*)d_out);
    state_kernel<<<2 * HV, 256, state_smem>>>(s0);
    opass_kernel<<<NCHUNK * HV, 256>>>((float*)d_out);
}

// round 11
// speedup vs baseline: 1.0490x; 1.0490x over previous
#include <cuda_runtime.h>
#include <cstdint>

#define T_STEPS 2048
#define HV 32
#define HKC 16
#define DHEAD 64
#define CONV_DIM_C 4096
#define KEY_DIM_C 1024
#define NCHUNK 32
#define SP 68          // smem row stride (floats), 16B-aligned

// ---- scratch (static __device__, no allocation) ----
__device__ float g_qn[T_STEPS * HKC * DHEAD];
__device__ float g_kn[T_STEPS * HKC * DHEAD];
__device__ float g_v [T_STEPS * HV * DHEAD];
__device__ float g_g   [T_STEPS * HV];
__device__ float g_beta[T_STEPS * HV];
__device__ float g_Qeff[NCHUNK * HV * 4096];
__device__ float g_G   [NCHUNK * HV * 4096];
__device__ float g_H   [NCHUNK * HV * 4096];
__device__ float g_ST  [NCHUNK * HV * 4096];   // chunk-start states, [v][k]

// ---- f32x2 packed FMA helpers ----
__device__ __forceinline__ void ffma2(unsigned long long& acc,
                                      unsigned long long a, unsigned long long b) {
    asm("fma.rn.f32x2 %0, %1, %2, %0;" : "+l"(acc) : "l"(a), "l"(b));
}
__device__ __forceinline__ float hsum(unsigned long long u) {
    float2 f = *reinterpret_cast<float2*>(&u);
    return f.x + f.y;
}

// ---- cp.async helpers ----
__device__ __forceinline__ void cp_async16(void* dst, const void* src) {
    uint32_t d = (uint32_t)__cvta_generic_to_shared(dst);
    asm volatile("cp.async.cg.shared.global [%0], [%1], 16;" :: "r"(d), "l"(src));
}
__device__ __forceinline__ void cp_commit() {
    asm volatile("cp.async.commit_group;");
}
__device__ __forceinline__ void cp_wait0() {
    asm volatile("cp.async.wait_group 0;");
}

// Single-X matmul (opass): Z[r][c] = sum_d X[r][d]*YT[c][d]
__device__ __forceinline__ void mm64x(const float* __restrict__ X,
                                      const float* __restrict__ YT,
                                      int r0, int tx, unsigned long long* __restrict__ acc)
{
#pragma unroll 4
    for (int d = 0; d < 64; d += 4) {
        ulonglong2 x0 = *(const ulonglong2*)(X + (r0 + 0) * SP + d);
        ulonglong2 x1 = *(const ulonglong2*)(X + (r0 + 1) * SP + d);
        ulonglong2 x2 = *(const ulonglong2*)(X + (r0 + 2) * SP + d);
        ulonglong2 x3 = *(const ulonglong2*)(X + (r0 + 3) * SP + d);
        ulonglong2 y0 = *(const ulonglong2*)(YT + (tx +  0) * SP + d);
        ulonglong2 y1 = *(const ulonglong2*)(YT + (tx + 16) * SP + d);
        ulonglong2 y2 = *(const ulonglong2*)(YT + (tx + 32) * SP + d);
        ulonglong2 y3 = *(const ulonglong2*)(YT + (tx + 48) * SP + d);
        ffma2(acc[ 0], x0.x, y0.x); ffma2(acc[ 0], x0.y, y0.y);
        ffma2(acc[ 1], x0.x, y1.x); ffma2(acc[ 1], x0.y, y1.y);
        ffma2(acc[ 2], x0.x, y2.x); ffma2(acc[ 2], x0.y, y2.y);
        ffma2(acc[ 3], x0.x, y3.x); ffma2(acc[ 3], x0.y, y3.y);
        ffma2(acc[ 4], x1.x, y0.x); ffma2(acc[ 4], x1.y, y0.y);
        ffma2(acc[ 5], x1.x, y1.x); ffma2(acc[ 5], x1.y, y1.y);
        ffma2(acc[ 6], x1.x, y2.x); ffma2(acc[ 6], x1.y, y2.y);
        ffma2(acc[ 7], x1.x, y3.x); ffma2(acc[ 7], x1.y, y3.y);
        ffma2(acc[ 8], x2.x, y0.x); ffma2(acc[ 8], x2.y, y0.y);
        ffma2(acc[ 9], x2.x, y1.x); ffma2(acc[ 9], x2.y, y1.y);
        ffma2(acc[10], x2.x, y2.x); ffma2(acc[10], x2.y, y2.y);
        ffma2(acc[11], x2.x, y3.x); ffma2(acc[11], x2.y, y3.y);
        ffma2(acc[12], x3.x, y0.x); ffma2(acc[12], x3.y, y0.y);
        ffma2(acc[13], x3.x, y1.x); ffma2(acc[13], x3.y, y1.y);
        ffma2(acc[14], x3.x, y2.x); ffma2(acc[14], x3.y, y2.y);
        ffma2(acc[15], x3.x, y3.x); ffma2(acc[15], x3.y, y3.y);
    }
}

// Dual-X matmul sharing Y loads (pass A): Z1 = X1@Y, Z2 = X2@Y.
__device__ __forceinline__ void mm64d(const float* __restrict__ X1,
                                      const float* __restrict__ X2,
                                      const float* __restrict__ YT,
                                      int r0, int tx,
                                      unsigned long long* __restrict__ a1,
                                      unsigned long long* __restrict__ a2)
{
#pragma unroll 2
    for (int d = 0; d < 64; d += 4) {
        ulonglong2 y0 = *(const ulonglong2*)(YT + (tx +  0) * SP + d);
        ulonglong2 y1 = *(const ulonglong2*)(YT + (tx + 16) * SP + d);
        ulonglong2 y2 = *(const ulonglong2*)(YT + (tx + 32) * SP + d);
        ulonglong2 y3 = *(const ulonglong2*)(YT + (tx + 48) * SP + d);
#pragma unroll
        for (int r = 0; r < 4; r++) {
            ulonglong2 x = *(const ulonglong2*)(X1 + (r0 + r) * SP + d);
            ffma2(a1[4*r + 0], x.x, y0.x); ffma2(a1[4*r + 0], x.y, y0.y);
            ffma2(a1[4*r + 1], x.x, y1.x); ffma2(a1[4*r + 1], x.y, y1.y);
            ffma2(a1[4*r + 2], x.x, y2.x); ffma2(a1[4*r + 2], x.y, y2.y);
            ffma2(a1[4*r + 3], x.x, y3.x); ffma2(a1[4*r + 3], x.y, y3.y);
        }
#pragma unroll
        for (int r = 0; r < 4; r++) {
            ulonglong2 x = *(const ulonglong2*)(X2 + (r0 + r) * SP + d);
            ffma2(a2[4*r + 0], x.x, y0.x); ffma2(a2[4*r + 0], x.y, y0.y);
            ffma2(a2[4*r + 1], x.x, y1.x); ffma2(a2[4*r + 1], x.y, y1.y);
            ffma2(a2[4*r + 2], x.x, y2.x); ffma2(a2[4*r + 2], x.y, y2.y);
            ffma2(a2[4*r + 3], x.x, y3.x); ffma2(a2[4*r + 3], x.y, y3.y);
        }
    }
}

// Dual-Y matmul sharing X loads (passes B'/C'): Z1 = X@Y1, Z2 = X@Y2.
__device__ __forceinline__ void mm64dy(const float* __restrict__ X,
                                       const float* __restrict__ YT1,
                                       const float* __restrict__ YT2,
                                       int r0, int tx,
                                       unsigned long long* __restrict__ a1,
                                       unsigned long long* __restrict__ a2)
{
#pragma unroll 2
    for (int d = 0; d < 64; d += 4) {
        ulonglong2 x0 = *(const ulonglong2*)(X + (r0 + 0) * SP + d);
        ulonglong2 x1 = *(const ulonglong2*)(X + (r0 + 1) * SP + d);
        ulonglong2 x2 = *(const ulonglong2*)(X + (r0 + 2) * SP + d);
        ulonglong2 x3 = *(const ulonglong2*)(X + (r0 + 3) * SP + d);
        {
            ulonglong2 y0 = *(const ulonglong2*)(YT1 + (tx +  0) * SP + d);
            ulonglong2 y1 = *(const ulonglong2*)(YT1 + (tx + 16) * SP + d);
            ulonglong2 y2 = *(const ulonglong2*)(YT1 + (tx + 32) * SP + d);
            ulonglong2 y3 = *(const ulonglong2*)(YT1 + (tx + 48) * SP + d);
            ffma2(a1[ 0], x0.x, y0.x); ffma2(a1[ 0], x0.y, y0.y);
            ffma2(a1[ 1], x0.x, y1.x); ffma2(a1[ 1], x0.y, y1.y);
            ffma2(a1[ 2], x0.x, y2.x); ffma2(a1[ 2], x0.y, y2.y);
            ffma2(a1[ 3], x0.x, y3.x); ffma2(a1[ 3], x0.y, y3.y);
            ffma2(a1[ 4], x1.x, y0.x); ffma2(a1[ 4], x1.y, y0.y);
            ffma2(a1[ 5], x1.x, y1.x); ffma2(a1[ 5], x1.y, y1.y);
            ffma2(a1[ 6], x1.x, y2.x); ffma2(a1[ 6], x1.y, y2.y);
            ffma2(a1[ 7], x1.x, y3.x); ffma2(a1[ 7], x1.y, y3.y);
            ffma2(a1[ 8], x2.x, y0.x); ffma2(a1[ 8], x2.y, y0.y);
            ffma2(a1[ 9], x2.x, y1.x); ffma2(a1[ 9], x2.y, y1.y);
            ffma2(a1[10], x2.x, y2.x); ffma2(a1[10], x2.y, y2.y);
            ffma2(a1[11], x2.x, y3.x); ffma2(a1[11], x2.y, y3.y);
            ffma2(a1[12], x3.x, y0.x); ffma2(a1[12], x3.y, y0.y);
            ffma2(a1[13], x3.x, y1.x); ffma2(a1[13], x3.y, y1.y);
            ffma2(a1[14], x3.x, y2.x); ffma2(a1[14], x3.y, y2.y);
            ffma2(a1[15], x3.x, y3.x); ffma2(a1[15], x3.y, y3.y);
        }
        {
            ulonglong2 y0 = *(const ulonglong2*)(YT2 + (tx +  0) * SP + d);
            ulonglong2 y1 = *(const ulonglong2*)(YT2 + (tx + 16) * SP + d);
            ulonglong2 y2 = *(const ulonglong2*)(YT2 + (tx + 32) * SP + d);
            ulonglong2 y3 = *(const ulonglong2*)(YT2 + (tx + 48) * SP + d);
            ffma2(a2[ 0], x0.x, y0.x); ffma2(a2[ 0], x0.y, y0.y);
            ffma2(a2[ 1], x0.x, y1.x); ffma2(a2[ 1], x0.y, y1.y);
            ffma2(a2[ 2], x0.x, y2.x); ffma2(a2[ 2], x0.y, y2.y);
            ffma2(a2[ 3], x0.x, y3.x); ffma2(a2[ 3], x0.y, y3.y);
            ffma2(a2[ 4], x1.x, y0.x); ffma2(a2[ 4], x1.y, y0.y);
            ffma2(a2[ 5], x1.x, y1.x); ffma2(a2[ 5], x1.y, y1.y);
            ffma2(a2[ 6], x1.x, y2.x); ffma2(a2[ 6], x1.y, y2.y);
            ffma2(a2[ 7], x1.x, y3.x); ffma2(a2[ 7], x1.y, y3.y);
            ffma2(a2[ 8], x2.x, y0.x); ffma2(a2[ 8], x2.y, y0.y);
            ffma2(a2[ 9], x2.x, y1.x); ffma2(a2[ 9], x2.y, y1.y);
            ffma2(a2[10], x2.x, y2.x); ffma2(a2[10], x2.y, y2.y);
            ffma2(a2[11], x2.x, y3.x); ffma2(a2[11], x2.y, y3.y);
            ffma2(a2[12], x3.x, y0.x); ffma2(a2[12], x3.y, y0.y);
            ffma2(a2[13], x3.x, y1.x); ffma2(a2[13], x3.y, y1.y);
            ffma2(a2[14], x3.x, y2.x); ffma2(a2[14], x3.y, y2.y);
            ffma2(a2[15], x3.x, y3.x); ffma2(a2[15], x3.y, y3.y);
        }
    }
}

// ---------------------------------------------------------------------------
// Kernel 1: conv1d(W=4)+silu+split+l2norm. 4 time-rows per CTA.
// ---------------------------------------------------------------------------
__global__ __launch_bounds__(256) void conv_kernel(
    const float* __restrict__ x,
    const float* __restrict__ cstate,
    const float* __restrict__ wgt)
{
    const int t0 = blockIdx.y * 4;
    const int c  = blockIdx.x * 1024 + threadIdx.x * 4;

    float4 w[4];
#pragma unroll
    for (int j = 0; j < 4; j++) w[j] = *(const float4*)(wgt + (size_t)(c + j) * 4);

    float4 xr[7];
#pragma unroll
    for (int rr = 0; rr < 7; rr++) {
        int r = t0 - 3 + rr;
        xr[rr] = (r >= 0) ? *(const float4*)(x + (size_t)r * CONV_DIM_C + c)
                          : *(const float4*)(cstate + (size_t)(r + 3) * CONV_DIM_C + c);
    }

    float acc[4][4];
#pragma unroll
    for (int tt = 0; tt < 4; tt++) {
        float xv0[4] = {xr[tt].x, xr[tt].y, xr[tt].z, xr[tt].w};
        float xv1[4] = {xr[tt+1].x, xr[tt+1].y, xr[tt+1].z, xr[tt+1].w};
        float xv2[4] = {xr[tt+2].x, xr[tt+2].y, xr[tt+2].z, xr[tt+2].w};
        float xv3[4] = {xr[tt+3].x, xr[tt+3].y, xr[tt+3].z, xr[tt+3].w};
#pragma unroll
        for (int j = 0; j < 4; j++) {
            float s = xv0[j] * w[j].x;
            s = fmaf(xv1[j], w[j].y, s);
            s = fmaf(xv2[j], w[j].z, s);
            s = fmaf(xv3[j], w[j].w, s);
            acc[tt][j] = s / (1.f + __expf(-s));
        }
    }

    if (c < 2 * KEY_DIM_C) {
        float ss[4];
#pragma unroll
        for (int tt = 0; tt < 4; tt++) {
            float s = 0.f;
#pragma unroll
            for (int j = 0; j < 4; j++) s = fmaf(acc[tt][j], acc[tt][j], s);
            s += __shfl_xor_sync(0xffffffffu, s, 1);
            s += __shfl_xor_sync(0xffffffffu, s, 2);
            s += __shfl_xor_sync(0xffffffffu, s, 4);
            s += __shfl_xor_sync(0xffffffffu, s, 8);
            ss[tt] = rsqrtf(s + 1e-6f);
        }
        const bool isq = (c < KEY_DIM_C);
#pragma unroll
        for (int tt = 0; tt < 4; tt++) {
            float sc = isq ? ss[tt] * 0.125f : ss[tt];
            float* dst = isq ? (g_qn + (size_t)(t0 + tt) * 1024 + c)
                             : (g_kn + (size_t)(t0 + tt) * 1024 + (c - KEY_DIM_C));
            *(float4*)dst = make_float4(acc[tt][0]*sc, acc[tt][1]*sc, acc[tt][2]*sc, acc[tt][3]*sc);
        }
    } else {
#pragma unroll
        for (int tt = 0; tt < 4; tt++) {
            float* dst = g_v + (size_t)(t0 + tt) * 2048 + (c - 2048);
            *(float4*)dst = make_float4(acc[tt][0], acc[tt][1], acc[tt][2], acc[tt][3]);
        }
    }
}

// ---------------------------------------------------------------------------
// Kernel 2: gates
// ---------------------------------------------------------------------------
__global__ void gates_kernel(
    const float* __restrict__ b, const float* __restrict__ a,
    const float* __restrict__ alog, const float* __restrict__ dtb)
{
    int i = blockIdx.x * blockDim.x + threadIdx.x;
    if (i >= T_STEPS * HV) return;
    int h = i & 31;
    g_beta[i] = 1.f / (1.f + expf(-b[i]));
    float xx = a[i] + dtb[h];
    float sp = (xx > 20.f) ? xx : log1pf(expf(xx));
    g_g[i] = -expf(alog[h]) * sp;
}

// ---------------------------------------------------------------------------
// Kernel 3: per-chunk WY-form precompute. 1024 CTAs, 256 threads, 2 CTA/SM.
// Pass A: Y-shared dual-X (M, Attn). Passes B'/C': X-shared dual-Y
// (Attn -> Qeff+Ointra; Cbar^T -> G+H) — 25% less LDS on the output GEMMs.
// ---------------------------------------------------------------------------
__global__ __launch_bounds__(256, 2) void chunk_kernel(float* __restrict__ out)
{
    extern __shared__ float sm[];
    float* sK   = sm;                 // [64][SP] K row-major, then Attn
    float* sKT  = sK  + 64 * SP;      // [64][SP] K^T (later Cbar^T)
    float* sQr  = sKT + 64 * SP;      // [64][SP] q normalized+scaled
    float* sM   = sQr + 64 * SP;      // [64][SP] M (solve matrix) -> W^T
    float* sW   = sM  + 64 * SP;      // [64][SP] W rhs/solved [t][k] -> P^T
    float* sP   = sW  + 64 * SP;      // [64][SP] beta*V / P [t][v]
    float* scg  = sP  + 64 * SP;      // [64]
    float* sE   = scg  + 64;
    float* sBeta= sE   + 64;
    float* sBE  = sBeta+ 64;
    float* sTmp = sBE  + 64;

    const int cid = blockIdx.x;
    const int i = cid >> 5;
    const int h = cid & 31;
    const int tid = threadIdx.x;
    const int ty = tid >> 4, tx = tid & 15;
    const int r0 = ty * 4;

    // ---- load K (+transpose), Q, V (row-major) ----
    const float* Kg = g_kn + (size_t)(i * 64) * 1024 + (h >> 1) * 64;
    const float* Qg = g_qn + (size_t)(i * 64) * 1024 + (h >> 1) * 64;
    const float* Vg = g_v  + (size_t)(i * 64) * 2048 + h * 64;
    for (int idx = tid; idx < 64 * 16; idx += 256) {
        int r = idx >> 4, c4 = (idx & 15) << 2;
        float4 kv = *(const float4*)(Kg + (size_t)r * 1024 + c4);
        sK[r * SP + c4 + 0] = kv.x; sK[r * SP + c4 + 1] = kv.y;
        sK[r * SP + c4 + 2] = kv.z; sK[r * SP + c4 + 3] = kv.w;
        sKT[(c4 + 0) * SP + r] = kv.x; sKT[(c4 + 1) * SP + r] = kv.y;
        sKT[(c4 + 2) * SP + r] = kv.z; sKT[(c4 + 3) * SP + r] = kv.w;
        float4 qv = *(const float4*)(Qg + (size_t)r * 1024 + c4);
        sQr[r * SP + c4 + 0] = qv.x; sQr[r * SP + c4 + 1] = qv.y;
        sQr[r * SP + c4 + 2] = qv.z; sQr[r * SP + c4 + 3] = qv.w;
        float4 vv = *(const float4*)(Vg + (size_t)r * 2048 + c4);
        *(float4*)(sP + r * SP + c4) = vv;
    }
    if (tid < 64) {
        scg[tid]   = g_g   [(size_t)(i * 64 + tid) * 32 + h];
        sBeta[tid] = g_beta[(size_t)(i * 64 + tid) * 32 + h];
    }
    __syncthreads();

    // ---- inclusive scan of log-decay ----
#pragma unroll
    for (int off = 1; off < 64; off <<= 1) {
        float v = 0.f;
        if (tid < 64) v = scg[tid] + ((tid >= off) ? scg[tid - off] : 0.f);
        __syncthreads();
        if (tid < 64) scg[tid] = v;
        __syncthreads();
    }
    if (tid < 64) {
        float e = __expf(scg[tid]);
        sE[tid] = e;
        sBE[tid] = e * sBeta[tid];
        sTmp[tid] = __expf(scg[63] - scg[tid]);
    }
    __syncthreads();

    // ---- RHS init (row-major): sW[t][k] = BE[t]*K[t][k]; sP[t][v] *= beta[t]
    for (int idx = tid; idx < 1024; idx += 256) {
        int r = idx >> 4, c4 = (idx & 15) << 2;
        float be = sBE[r], bb = sBeta[r];
        float4 kv = *(const float4*)(sK + r * SP + c4);
        *(float4*)(sW + r * SP + c4) =
            make_float4(be * kv.x, be * kv.y, be * kv.z, be * kv.w);
        float4 pv = *(const float4*)(sP + r * SP + c4);
        *(float4*)(sP + r * SP + c4) =
            make_float4(bb * pv.x, bb * pv.y, bb * pv.z, bb * pv.w);
    }

    unsigned long long a1[16], a2[16];

    // ---- pass A: Y=K; X1=K -> M, X2=Q -> Attn ----
#pragma unroll
    for (int j = 0; j < 16; j++) { a1[j] = 0ull; a2[j] = 0ull; }
    mm64d(sK, sQr, sK, r0, tx, a1, a2);
    __syncthreads();   // all reads of sK (and RHS init) done before overwrite
#pragma unroll
    for (int ri = 0; ri < 4; ri++) {
        int t = r0 + ri;
        float bt = sBeta[t], ct = scg[t];
#pragma unroll
        for (int ci = 0; ci < 4; ci++) {
            int s = tx + 16 * ci;
            float esc = __expf(ct - scg[s]);
            sM[t * SP + s] = (s < t) ? bt * hsum(a1[ri * 4 + ci]) * esc : 0.f;
            sK[t * SP + s] = (s <= t) ? hsum(a2[ri * 4 + ci]) * esc : 0.f;   // Attn
        }
    }
    __syncthreads();

    // ---- solve (I+M)X = RHS, row-major layout: X[t][cc], lane-contiguous ----
    if (tid < 128) {
        float* X = (tid < 64) ? sW : sP;
        const int cc = tid & 63;
        for (int t = 0; t < 64; t++) {
            float r = X[t * SP + cc];
            const float* Mr = sM + t * SP;
            float b0 = 0.f, b1 = 0.f, b2 = 0.f, b3 = 0.f;
            int s = 0;
            for (; s + 4 <= t; s += 4) {
                b0 = fmaf(Mr[s + 0], X[(s + 0) * SP + cc], b0);
                b1 = fmaf(Mr[s + 1], X[(s + 1) * SP + cc], b1);
                b2 = fmaf(Mr[s + 2], X[(s + 2) * SP + cc], b2);
                b3 = fmaf(Mr[s + 3], X[(s + 3) * SP + cc], b3);
            }
            for (; s < t; s++) b0 = fmaf(Mr[s], X[s * SP + cc], b0);
            X[t * SP + cc] = r - ((b0 + b1) + (b2 + b3));
        }
    }
    __syncthreads();

    // ---- transpose W: sW[t][k] -> sM[k][t]; scale sKT -> Cbar^T ----
    for (int idx = tid; idx < 1024; idx += 256) {
        int r = idx >> 4, c4 = (idx & 15) << 2;
        float4 w = *(const float4*)(sW + r * SP + c4);
        sM[(c4 + 0) * SP + r] = w.x; sM[(c4 + 1) * SP + r] = w.y;
        sM[(c4 + 2) * SP + r] = w.z; sM[(c4 + 3) * SP + r] = w.w;
    }
    for (int idx = tid; idx < 4096; idx += 256) {
        int r = idx >> 6, s = idx & 63;
        sKT[r * SP + s] *= sTmp[s];
    }
    __syncthreads();

    // ---- transpose P: sP[t][v] -> sW[v][t] ----
    for (int idx = tid; idx < 1024; idx += 256) {
        int r = idx >> 4, c4 = (idx & 15) << 2;
        float4 p = *(const float4*)(sP + r * SP + c4);
        sW[(c4 + 0) * SP + r] = p.x; sW[(c4 + 1) * SP + r] = p.y;
        sW[(c4 + 2) * SP + r] = p.z; sW[(c4 + 3) * SP + r] = p.w;
    }
    __syncthreads();

    const size_t base = ((size_t)(i * 32 + h)) << 12;

    // ---- pass B': X=Attn; Y1=W^T (sM) -> Qeff, Y2=P^T (sW) -> Ointra ----
#pragma unroll
    for (int j = 0; j < 16; j++) { a1[j] = 0ull; a2[j] = 0ull; }
    mm64dy(sK, sM, sW, r0, tx, a1, a2);
#pragma unroll
    for (int ri = 0; ri < 4; ri++) {
        int t = r0 + ri;
        float et = sE[t];
        float* op = out + (size_t)(i * 64 + t) * 2048 + h * 64;
#pragma unroll
        for (int ci = 0; ci < 4; ci++) {
            int s = tx + 16 * ci;
            g_Qeff[base + t * 64 + s] = fmaf(et, sQr[t * SP + s], -hsum(a1[ri * 4 + ci]));
            op[s] = hsum(a2[ri * 4 + ci]);
        }
    }

    // ---- pass C': X=Cbar^T; Y1=W^T -> G, Y2=P^T -> H ----
#pragma unroll
    for (int j = 0; j < 16; j++) { a1[j] = 0ull; a2[j] = 0ull; }
    mm64dy(sKT, sM, sW, r0, tx, a1, a2);
    {
        float b63 = sE[63];
#pragma unroll
        for (int ri = 0; ri < 4; ri++) {
            int k = r0 + ri;
#pragma unroll
            for (int ci = 0; ci < 4; ci++) {
                int s = tx + 16 * ci;
                g_G[base + k * 64 + s] = ((k == s) ? b63 : 0.f) - hsum(a1[ri * 4 + ci]);
                g_H[base + k * 64 + s] = hsum(a2[ri * 4 + ci]);
            }
        }
    }
}

// ---------------------------------------------------------------------------
// Kernel 4: state pass (R7 proven, 63.5us). 64 CTAs = (head, v-half) x 256.
// ---------------------------------------------------------------------------
__global__ __launch_bounds__(256) void state_kernel(const float* __restrict__ S0)
{
    extern __shared__ float sms[];
    float* sG0 = sms;                 // [64][SP]
    float* sG1 = sG0 + 64 * SP;
    float* sS0 = sG1 + 64 * SP;       // [32 v][SP] (k contiguous)
    float* sS1 = sS0 + 32 * SP;

    const int h = blockIdx.x >> 1;
    const int vbase = (blockIdx.x & 1) * 32;
    const int tid = threadIdx.x;
    const int wrp = tid >> 5, l = tid & 31;
    const int k0 = wrp * 8;
    const int vloc = l;
    const int vglob = vbase + vloc;

    const size_t hbase = ((size_t)h) << 12;

    for (int idx = tid; idx < 2048; idx += 256) {
        int k = idx >> 5, v = idx & 31;
        sS0[v * SP + k] = S0[hbase + k * 64 + vbase + v];
    }
#pragma unroll
    for (int j = 0; j < 4; j++) {
        int seg = tid + j * 256;
        int r = seg >> 4, c4 = (seg & 15) << 2;
        cp_async16(sG0 + r * SP + c4, g_G + hbase + r * 64 + c4);
    }
    cp_commit();
    float hcur[8];
#pragma unroll
    for (int r = 0; r < 8; r++)
        hcur[r] = g_H[hbase + (k0 + r) * 64 + vglob];
    cp_wait0();
    __syncthreads();

    float* Scur = sS0; float* Snxt = sS1;
    float* Gcur = sG0; float* Gnxt = sG1;

    for (int i = 0; i < NCHUNK; i++) {
        const size_t basei = ((size_t)(i * 32 + h)) << 12;
        for (int idx = tid; idx < 512; idx += 256) {
            int v = idx >> 4, k4 = (idx & 15) << 2;
            *(float4*)(g_ST + basei + (vbase + v) * 64 + k4) =
                *(const float4*)(Scur + v * SP + k4);
        }
        if (i == NCHUNK - 1) break;

        const size_t basen = ((size_t)((i + 1) * 32 + h)) << 12;
#pragma unroll
        for (int j = 0; j < 4; j++) {
            int seg = tid + j * 256;
            int r = seg >> 4, c4 = (seg & 15) << 2;
            cp_async16(Gnxt + r * SP + c4, g_G + basen + r * 64 + c4);
        }
        cp_commit();
        float hpre[8];
#pragma unroll
        for (int r = 0; r < 8; r++)
            hpre[r] = g_H[basen + (k0 + r) * 64 + vglob];

        unsigned long long acc[8];
#pragma unroll
        for (int j = 0; j < 8; j++) acc[j] = 0ull;
#pragma unroll 4
        for (int d = 0; d < 64; d += 4) {
            ulonglong2 y = *(const ulonglong2*)(Scur + vloc * SP + d);
#pragma unroll
            for (int r = 0; r < 8; r++) {
                ulonglong2 x = *(const ulonglong2*)(Gcur + (k0 + r) * SP + d);
                ffma2(acc[r], x.x, y.x); ffma2(acc[r], x.y, y.y);
            }
        }
        {
            float4 o0, o1;
            o0.x = hsum(acc[0]) + hcur[0]; o0.y = hsum(acc[1]) + hcur[1];
            o0.z = hsum(acc[2]) + hcur[2]; o0.w = hsum(acc[3]) + hcur[3];
            o1.x = hsum(acc[4]) + hcur[4]; o1.y = hsum(acc[5]) + hcur[5];
            o1.z = hsum(acc[6]) + hcur[6]; o1.w = hsum(acc[7]) + hcur[7];
            *(float4*)(Snxt + vloc * SP + k0)     = o0;
            *(float4*)(Snxt + vloc * SP + k0 + 4) = o1;
        }
#pragma unroll
        for (int j = 0; j < 8; j++) hcur[j] = hpre[j];
        cp_wait0();
        __syncthreads();
        float* t1 = Scur; Scur = Snxt; Snxt = t1;
        float* t2 = Gcur; Gcur = Gnxt; Gnxt = t2;
    }
}

// ---------------------------------------------------------------------------
// Kernel 5: O pass (fully parallel). out += Qeff_i @ S_i. 1024 CTAs.
// ---------------------------------------------------------------------------
__global__ __launch_bounds__(256) void opass_kernel(float* __restrict__ out)
{
    __shared__ float sQe[64 * SP];
    __shared__ float sST[64 * SP];

    const int bi = blockIdx.x;
    const int i = bi >> 5;
    const int h = bi & 31;
    const int tid = threadIdx.x;
    const int ty = tid >> 4, tx = tid & 15;
    const int r0 = ty * 4;

    const size_t base = ((size_t)(i * 32 + h)) << 12;
    for (int idx = tid; idx < 1024; idx += 256) {
        int r = idx >> 4, c4 = (idx & 15) << 2;
        float4 q = *(const float4*)(g_Qeff + base + r * 64 + c4);
        sQe[r * SP + c4 + 0] = q.x; sQe[r * SP + c4 + 1] = q.y;
        sQe[r * SP + c4 + 2] = q.z; sQe[r * SP + c4 + 3] = q.w;
        float4 s = *(const float4*)(g_ST + base + r * 64 + c4);
        sST[r * SP + c4 + 0] = s.x; sST[r * SP + c4 + 1] = s.y;
        sST[r * SP + c4 + 2] = s.z; sST[r * SP + c4 + 3] = s.w;
    }
    __syncthreads();

    unsigned long long acc[16];
#pragma unroll
    for (int j = 0; j < 16; j++) acc[j] = 0ull;
    mm64x(sQe, sST, r0, tx, acc);

#pragma unroll
    for (int ri = 0; ri < 4; ri++) {
        int t = r0 + ri;
        float* op = out + (size_t)(i * 64 + t) * 2048 + h * 64;
#pragma unroll
        for (int ci = 0; ci < 4; ci++) {
            int s = tx + 16 * ci;
            op[s] += hsum(acc[ri * 4 + ci]);
        }
    }
}

// ---------------------------------------------------------------------------
extern "C" void kernel_launch(void* const* d_in, const int* in_sizes, int n_in,
                              void* d_out, int out_size)
{
    const float* x    = (const float*)d_in[0];
    const float* cs   = (const float*)d_in[1];
    const float* s0   = (const float*)d_in[2];
    const float* b    = (const float*)d_in[3];
    const float* a    = (const float*)d_in[4];
    const float* w    = (const float*)d_in[5];
    const float* alog = (const float*)d_in[6];
    const float* dtb  = (const float*)d_in[7];

    const int chunk_smem = (6 * 64 * SP + 5 * 64) * sizeof(float);      // ~105.7 KB
    const int state_smem = (2 * 64 * SP + 2 * 32 * SP) * sizeof(float); // ~52.2 KB
    static bool attr_done = false;
    if (!attr_done) {
        cudaFuncSetAttribute(chunk_kernel,
                             cudaFuncAttributeMaxDynamicSharedMemorySize, chunk_smem);
        cudaFuncSetAttribute(state_kernel,
                             cudaFuncAttributeMaxDynamicSharedMemorySize, state_smem);
        attr_done = true;
    }

    conv_kernel<<<dim3(4, T_STEPS / 4), 256>>>(x, cs, w);
    gates_kernel<<<(T_STEPS * HV + 255) / 256, 256>>>(b, a, alog, dtb);
    chunk_kernel<<<NCHUNK * HV, 256, chunk_smem>>>((float*)d_out);
    state_kernel<<<2 * HV, 256, state_smem>>>(s0);
    opass_kernel<<<NCHUNK * HV, 256>>>((float*)d_out);
}

// round 12
// speedup vs baseline: 1.0718x; 1.0218x over previous
#include <cuda_runtime.h>
#include <cstdint>

#define T_STEPS 2048
#define HV 32
#define HKC 16
#define DHEAD 64
#define CONV_DIM_C 4096
#define KEY_DIM_C 1024
#define NCHUNK 32
#define SP 68          // smem row stride (floats), 16B-aligned

// ---- scratch (static __device__, no allocation) ----
__device__ float g_qn[T_STEPS * HKC * DHEAD];
__device__ float g_kn[T_STEPS * HKC * DHEAD];
__device__ float g_v [T_STEPS * HV * DHEAD];
__device__ float g_g   [T_STEPS * HV];
__device__ float g_beta[T_STEPS * HV];
__device__ float g_Qeff[NCHUNK * HV * 4096];
__device__ float g_G   [NCHUNK * HV * 4096];
__device__ float g_H   [NCHUNK * HV * 4096];
__device__ float g_ST  [NCHUNK * HV * 4096];   // chunk-start states, [v][k]

// ---- f32x2 packed FMA helpers ----
__device__ __forceinline__ void ffma2(unsigned long long& acc,
                                      unsigned long long a, unsigned long long b) {
    asm("fma.rn.f32x2 %0, %1, %2, %0;" : "+l"(acc) : "l"(a), "l"(b));
}
__device__ __forceinline__ float hsum(unsigned long long u) {
    float2 f = *reinterpret_cast<float2*>(&u);
    return f.x + f.y;
}

// ---- cp.async helpers ----
__device__ __forceinline__ void cp_async16(void* dst, const void* src) {
    uint32_t d = (uint32_t)__cvta_generic_to_shared(dst);
    asm volatile("cp.async.cg.shared.global [%0], [%1], 16;" :: "r"(d), "l"(src));
}
__device__ __forceinline__ void cp_commit() {
    asm volatile("cp.async.commit_group;");
}
__device__ __forceinline__ void cp_wait0() {
    asm volatile("cp.async.wait_group 0;");
}
__device__ __forceinline__ void cp_wait1() {
    asm volatile("cp.async.wait_group 1;");
}

// Single-X matmul: Z[r][c] = sum_d X[r][d]*YT[c][d]
__device__ __forceinline__ void mm64x(const float* __restrict__ X,
                                      const float* __restrict__ YT,
                                      int r0, int tx, unsigned long long* __restrict__ acc)
{
#pragma unroll 4
    for (int d = 0; d < 64; d += 4) {
        ulonglong2 x0 = *(const ulonglong2*)(X + (r0 + 0) * SP + d);
        ulonglong2 x1 = *(const ulonglong2*)(X + (r0 + 1) * SP + d);
        ulonglong2 x2 = *(const ulonglong2*)(X + (r0 + 2) * SP + d);
        ulonglong2 x3 = *(const ulonglong2*)(X + (r0 + 3) * SP + d);
        ulonglong2 y0 = *(const ulonglong2*)(YT + (tx +  0) * SP + d);
        ulonglong2 y1 = *(const ulonglong2*)(YT + (tx + 16) * SP + d);
        ulonglong2 y2 = *(const ulonglong2*)(YT + (tx + 32) * SP + d);
        ulonglong2 y3 = *(const ulonglong2*)(YT + (tx + 48) * SP + d);
        ffma2(acc[ 0], x0.x, y0.x); ffma2(acc[ 0], x0.y, y0.y);
        ffma2(acc[ 1], x0.x, y1.x); ffma2(acc[ 1], x0.y, y1.y);
        ffma2(acc[ 2], x0.x, y2.x); ffma2(acc[ 2], x0.y, y2.y);
        ffma2(acc[ 3], x0.x, y3.x); ffma2(acc[ 3], x0.y, y3.y);
        ffma2(acc[ 4], x1.x, y0.x); ffma2(acc[ 4], x1.y, y0.y);
        ffma2(acc[ 5], x1.x, y1.x); ffma2(acc[ 5], x1.y, y1.y);
        ffma2(acc[ 6], x1.x, y2.x); ffma2(acc[ 6], x1.y, y2.y);
        ffma2(acc[ 7], x1.x, y3.x); ffma2(acc[ 7], x1.y, y3.y);
        ffma2(acc[ 8], x2.x, y0.x); ffma2(acc[ 8], x2.y, y0.y);
        ffma2(acc[ 9], x2.x, y1.x); ffma2(acc[ 9], x2.y, y1.y);
        ffma2(acc[10], x2.x, y2.x); ffma2(acc[10], x2.y, y2.y);
        ffma2(acc[11], x2.x, y3.x); ffma2(acc[11], x2.y, y3.y);
        ffma2(acc[12], x3.x, y0.x); ffma2(acc[12], x3.y, y0.y);
        ffma2(acc[13], x3.x, y1.x); ffma2(acc[13], x3.y, y1.y);
        ffma2(acc[14], x3.x, y2.x); ffma2(acc[14], x3.y, y2.y);
        ffma2(acc[15], x3.x, y3.x); ffma2(acc[15], x3.y, y3.y);
    }
}

// Dual-X matmul sharing Y loads (pass A): Z1 = X1@Y, Z2 = X2@Y.
__device__ __forceinline__ void mm64d(const float* __restrict__ X1,
                                      const float* __restrict__ X2,
                                      const float* __restrict__ YT,
                                      int r0, int tx,
                                      unsigned long long* __restrict__ a1,
                                      unsigned long long* __restrict__ a2)
{
#pragma unroll 2
    for (int d = 0; d < 64; d += 4) {
        ulonglong2 y0 = *(const ulonglong2*)(YT + (tx +  0) * SP + d);
        ulonglong2 y1 = *(const ulonglong2*)(YT + (tx + 16) * SP + d);
        ulonglong2 y2 = *(const ulonglong2*)(YT + (tx + 32) * SP + d);
        ulonglong2 y3 = *(const ulonglong2*)(YT + (tx + 48) * SP + d);
#pragma unroll
        for (int r = 0; r < 4; r++) {
            ulonglong2 x = *(const ulonglong2*)(X1 + (r0 + r) * SP + d);
            ffma2(a1[4*r + 0], x.x, y0.x); ffma2(a1[4*r + 0], x.y, y0.y);
            ffma2(a1[4*r + 1], x.x, y1.x); ffma2(a1[4*r + 1], x.y, y1.y);
            ffma2(a1[4*r + 2], x.x, y2.x); ffma2(a1[4*r + 2], x.y, y2.y);
            ffma2(a1[4*r + 3], x.x, y3.x); ffma2(a1[4*r + 3], x.y, y3.y);
        }
#pragma unroll
        for (int r = 0; r < 4; r++) {
            ulonglong2 x = *(const ulonglong2*)(X2 + (r0 + r) * SP + d);
            ffma2(a2[4*r + 0], x.x, y0.x); ffma2(a2[4*r + 0], x.y, y0.y);
            ffma2(a2[4*r + 1], x.x, y1.x); ffma2(a2[4*r + 1], x.y, y1.y);
            ffma2(a2[4*r + 2], x.x, y2.x); ffma2(a2[4*r + 2], x.y, y2.y);
            ffma2(a2[4*r + 3], x.x, y3.x); ffma2(a2[4*r + 3], x.y, y3.y);
        }
    }
}

// ---------------------------------------------------------------------------
// Kernel 1: conv1d(W=4)+silu+split+l2norm. 4 time-rows per CTA.
// ---------------------------------------------------------------------------
__global__ __launch_bounds__(256) void conv_kernel(
    const float* __restrict__ x,
    const float* __restrict__ cstate,
    const float* __restrict__ wgt)
{
    const int t0 = blockIdx.y * 4;
    const int c  = blockIdx.x * 1024 + threadIdx.x * 4;

    float4 w[4];
#pragma unroll
    for (int j = 0; j < 4; j++) w[j] = *(const float4*)(wgt + (size_t)(c + j) * 4);

    float4 xr[7];
#pragma unroll
    for (int rr = 0; rr < 7; rr++) {
        int r = t0 - 3 + rr;
        xr[rr] = (r >= 0) ? *(const float4*)(x + (size_t)r * CONV_DIM_C + c)
                          : *(const float4*)(cstate + (size_t)(r + 3) * CONV_DIM_C + c);
    }

    float acc[4][4];
#pragma unroll
    for (int tt = 0; tt < 4; tt++) {
        float xv0[4] = {xr[tt].x, xr[tt].y, xr[tt].z, xr[tt].w};
        float xv1[4] = {xr[tt+1].x, xr[tt+1].y, xr[tt+1].z, xr[tt+1].w};
        float xv2[4] = {xr[tt+2].x, xr[tt+2].y, xr[tt+2].z, xr[tt+2].w};
        float xv3[4] = {xr[tt+3].x, xr[tt+3].y, xr[tt+3].z, xr[tt+3].w};
#pragma unroll
        for (int j = 0; j < 4; j++) {
            float s = xv0[j] * w[j].x;
            s = fmaf(xv1[j], w[j].y, s);
            s = fmaf(xv2[j], w[j].z, s);
            s = fmaf(xv3[j], w[j].w, s);
            acc[tt][j] = s / (1.f + __expf(-s));
        }
    }

    if (c < 2 * KEY_DIM_C) {
        float ss[4];
#pragma unroll
        for (int tt = 0; tt < 4; tt++) {
            float s = 0.f;
#pragma unroll
            for (int j = 0; j < 4; j++) s = fmaf(acc[tt][j], acc[tt][j], s);
            s += __shfl_xor_sync(0xffffffffu, s, 1);
            s += __shfl_xor_sync(0xffffffffu, s, 2);
            s += __shfl_xor_sync(0xffffffffu, s, 4);
            s += __shfl_xor_sync(0xffffffffu, s, 8);
            ss[tt] = rsqrtf(s + 1e-6f);
        }
        const bool isq = (c < KEY_DIM_C);
#pragma unroll
        for (int tt = 0; tt < 4; tt++) {
            float sc = isq ? ss[tt] * 0.125f : ss[tt];
            float* dst = isq ? (g_qn + (size_t)(t0 + tt) * 1024 + c)
                             : (g_kn + (size_t)(t0 + tt) * 1024 + (c - KEY_DIM_C));
            *(float4*)dst = make_float4(acc[tt][0]*sc, acc[tt][1]*sc, acc[tt][2]*sc, acc[tt][3]*sc);
        }
    } else {
#pragma unroll
        for (int tt = 0; tt < 4; tt++) {
            float* dst = g_v + (size_t)(t0 + tt) * 2048 + (c - 2048);
            *(float4*)dst = make_float4(acc[tt][0], acc[tt][1], acc[tt][2], acc[tt][3]);
        }
    }
}

// ---------------------------------------------------------------------------
// Kernel 2: gates
// ---------------------------------------------------------------------------
__global__ void gates_kernel(
    const float* __restrict__ b, const float* __restrict__ a,
    const float* __restrict__ alog, const float* __restrict__ dtb)
{
    int i = blockIdx.x * blockDim.x + threadIdx.x;
    if (i >= T_STEPS * HV) return;
    int h = i & 31;
    g_beta[i] = 1.f / (1.f + expf(-b[i]));
    float xx = a[i] + dtb[h];
    float sp = (xx > 20.f) ? xx : log1pf(expf(xx));
    g_g[i] = -expf(alog[h]) * sp;
}

// ---------------------------------------------------------------------------
// Kernel 3: per-chunk WY-form precompute (R9 proven). 1024 CTAs, 256 thr.
// ---------------------------------------------------------------------------
__global__ __launch_bounds__(256, 2) void chunk_kernel(float* __restrict__ out)
{
    extern __shared__ float sm[];
    float* sK   = sm;                 // [64][SP] K row-major, then Attn
    float* sKT  = sK  + 64 * SP;      // [64][SP] K^T (later Cbar^T)
    float* sQr  = sKT + 64 * SP;      // [64][SP] q normalized+scaled
    float* sM   = sQr + 64 * SP;      // [64][SP] M (solve matrix) -> W^T
    float* sW   = sM  + 64 * SP;      // [64][SP] W rhs/solved [t][k] -> P^T
    float* sP   = sW  + 64 * SP;      // [64][SP] beta*V / P [t][v]
    float* scg  = sP  + 64 * SP;      // [64]
    float* sE   = scg  + 64;
    float* sBeta= sE   + 64;
    float* sBE  = sBeta+ 64;
    float* sTmp = sBE  + 64;

    const int cid = blockIdx.x;
    const int i = cid >> 5;
    const int h = cid & 31;
    const int tid = threadIdx.x;
    const int ty = tid >> 4, tx = tid & 15;
    const int r0 = ty * 4;

    // ---- load K (+transpose), Q, V (row-major) ----
    const float* Kg = g_kn + (size_t)(i * 64) * 1024 + (h >> 1) * 64;
    const float* Qg = g_qn + (size_t)(i * 64) * 1024 + (h >> 1) * 64;
    const float* Vg = g_v  + (size_t)(i * 64) * 2048 + h * 64;
    for (int idx = tid; idx < 64 * 16; idx += 256) {
        int r = idx >> 4, c4 = (idx & 15) << 2;
        float4 kv = *(const float4*)(Kg + (size_t)r * 1024 + c4);
        sK[r * SP + c4 + 0] = kv.x; sK[r * SP + c4 + 1] = kv.y;
        sK[r * SP + c4 + 2] = kv.z; sK[r * SP + c4 + 3] = kv.w;
        sKT[(c4 + 0) * SP + r] = kv.x; sKT[(c4 + 1) * SP + r] = kv.y;
        sKT[(c4 + 2) * SP + r] = kv.z; sKT[(c4 + 3) * SP + r] = kv.w;
        float4 qv = *(const float4*)(Qg + (size_t)r * 1024 + c4);
        sQr[r * SP + c4 + 0] = qv.x; sQr[r * SP + c4 + 1] = qv.y;
        sQr[r * SP + c4 + 2] = qv.z; sQr[r * SP + c4 + 3] = qv.w;
        float4 vv = *(const float4*)(Vg + (size_t)r * 2048 + c4);
        *(float4*)(sP + r * SP + c4) = vv;
    }
    if (tid < 64) {
        scg[tid]   = g_g   [(size_t)(i * 64 + tid) * 32 + h];
        sBeta[tid] = g_beta[(size_t)(i * 64 + tid) * 32 + h];
    }
    __syncthreads();

    // ---- inclusive scan of log-decay ----
#pragma unroll
    for (int off = 1; off < 64; off <<= 1) {
        float v = 0.f;
        if (tid < 64) v = scg[tid] + ((tid >= off) ? scg[tid - off] : 0.f);
        __syncthreads();
        if (tid < 64) scg[tid] = v;
        __syncthreads();
    }
    if (tid < 64) {
        float e = __expf(scg[tid]);
        sE[tid] = e;
        sBE[tid] = e * sBeta[tid];
        sTmp[tid] = __expf(scg[63] - scg[tid]);
    }
    __syncthreads();

    // ---- RHS init (row-major): sW[t][k] = BE[t]*K[t][k]; sP[t][v] *= beta[t]
    for (int idx = tid; idx < 1024; idx += 256) {
        int r = idx >> 4, c4 = (idx & 15) << 2;
        float be = sBE[r], bb = sBeta[r];
        float4 kv = *(const float4*)(sK + r * SP + c4);
        *(float4*)(sW + r * SP + c4) =
            make_float4(be * kv.x, be * kv.y, be * kv.z, be * kv.w);
        float4 pv = *(const float4*)(sP + r * SP + c4);
        *(float4*)(sP + r * SP + c4) =
            make_float4(bb * pv.x, bb * pv.y, bb * pv.z, bb * pv.w);
    }

    unsigned long long a1[16], a2[16];

    // ---- pass A: Y=K; X1=K -> M, X2=Q -> Attn ----
#pragma unroll
    for (int j = 0; j < 16; j++) { a1[j] = 0ull; a2[j] = 0ull; }
    mm64d(sK, sQr, sK, r0, tx, a1, a2);
    __syncthreads();   // all reads of sK (and RHS init) done before overwrite
#pragma unroll
    for (int ri = 0; ri < 4; ri++) {
        int t = r0 + ri;
        float bt = sBeta[t], ct = scg[t];
#pragma unroll
        for (int ci = 0; ci < 4; ci++) {
            int s = tx + 16 * ci;
            float esc = __expf(ct - scg[s]);
            sM[t * SP + s] = (s < t) ? bt * hsum(a1[ri * 4 + ci]) * esc : 0.f;
            sK[t * SP + s] = (s <= t) ? hsum(a2[ri * 4 + ci]) * esc : 0.f;   // Attn
        }
    }
    __syncthreads();

    // ---- solve (I+M)X = RHS, row-major layout: X[t][cc], lane-contiguous ----
    if (tid < 128) {
        float* X = (tid < 64) ? sW : sP;
        const int cc = tid & 63;
        for (int t = 0; t < 64; t++) {
            float r = X[t * SP + cc];
            const float* Mr = sM + t * SP;
            float b0 = 0.f, b1 = 0.f, b2 = 0.f, b3 = 0.f;
            int s = 0;
            for (; s + 4 <= t; s += 4) {
                b0 = fmaf(Mr[s + 0], X[(s + 0) * SP + cc], b0);
                b1 = fmaf(Mr[s + 1], X[(s + 1) * SP + cc], b1);
                b2 = fmaf(Mr[s + 2], X[(s + 2) * SP + cc], b2);
                b3 = fmaf(Mr[s + 3], X[(s + 3) * SP + cc], b3);
            }
            for (; s < t; s++) b0 = fmaf(Mr[s], X[s * SP + cc], b0);
            X[t * SP + cc] = r - ((b0 + b1) + (b2 + b3));
        }
    }
    __syncthreads();

    // ---- transpose W: sW[t][k] -> sM[k][t]; scale sKT -> Cbar^T ----
    for (int idx = tid; idx < 1024; idx += 256) {
        int r = idx >> 4, c4 = (idx & 15) << 2;
        float4 w = *(const float4*)(sW + r * SP + c4);
        sM[(c4 + 0) * SP + r] = w.x; sM[(c4 + 1) * SP + r] = w.y;
        sM[(c4 + 2) * SP + r] = w.z; sM[(c4 + 3) * SP + r] = w.w;
    }
    for (int idx = tid; idx < 4096; idx += 256) {
        int r = idx >> 6, s = idx & 63;
        sKT[r * SP + s] *= sTmp[s];
    }
    __syncthreads();

    // ---- transpose P: sP[t][v] -> sW[v][t] ----
    for (int idx = tid; idx < 1024; idx += 256) {
        int r = idx >> 4, c4 = (idx & 15) << 2;
        float4 p = *(const float4*)(sP + r * SP + c4);
        sW[(c4 + 0) * SP + r] = p.x; sW[(c4 + 1) * SP + r] = p.y;
        sW[(c4 + 2) * SP + r] = p.z; sW[(c4 + 3) * SP + r] = p.w;
    }
    __syncthreads();

    const size_t base = ((size_t)(i * 32 + h)) << 12;

    // ---- pass B: Y=W^T (sM); X1=Attn -> Qeff, X2=Cbar^T -> G ----
#pragma unroll
    for (int j = 0; j < 16; j++) { a1[j] = 0ull; a2[j] = 0ull; }
    mm64d(sK, sKT, sM, r0, tx, a1, a2);
    {
        float b63 = sE[63];
#pragma unroll
        for (int ri = 0; ri < 4; ri++) {
            int t = r0 + ri;
            float et = sE[t];
#pragma unroll
            for (int ci = 0; ci < 4; ci++) {
                int s = tx + 16 * ci;
                g_Qeff[base + t * 64 + s] = fmaf(et, sQr[t * SP + s], -hsum(a1[ri * 4 + ci]));
                g_G   [base + t * 64 + s] = ((t == s) ? b63 : 0.f) - hsum(a2[ri * 4 + ci]);
            }
        }
    }

    // ---- pass C: Y=P^T (sW); X1=Attn -> Ointra, X2=Cbar^T -> H ----
#pragma unroll
    for (int j = 0; j < 16; j++) { a1[j] = 0ull; a2[j] = 0ull; }
    mm64d(sK, sKT, sW, r0, tx, a1, a2);
#pragma unroll
    for (int ri = 0; ri < 4; ri++) {
        int t = r0 + ri;
        float* op = out + (size_t)(i * 64 + t) * 2048 + h * 64;
#pragma unroll
        for (int ci = 0; ci < 4; ci++) {
            int s = tx + 16 * ci;
            op[s] = hsum(a1[ri * 4 + ci]);
            g_H[base + t * 64 + s] = hsum(a2[ri * 4 + ci]);
        }
    }
}

// ---------------------------------------------------------------------------
// Kernel 4: state pass — depth-2 cp.async pipeline (3 G buffers).
// 64 CTAs = (head, v-half) x 256 threads. S_{i+1} = G_i S_i + H_i.
// G(i) is waited with wait_group 1 while G(i+1) stays in flight; G(i+2)
// is issued right after the barrier (no WAR race: its buffer's readers
// finished before this barrier).
// ---------------------------------------------------------------------------
__global__ __launch_bounds__(256) void state_kernel(const float* __restrict__ S0)
{
    extern __shared__ float sms[];
    float* sGb0 = sms;                  // [64][SP] x3 rotating G buffers
    float* sGb1 = sGb0 + 64 * SP;
    float* sGb2 = sGb1 + 64 * SP;
    float* sS0  = sGb2 + 64 * SP;       // [32 v][SP] (k contiguous)
    float* sS1  = sS0  + 32 * SP;

    const int h = blockIdx.x >> 1;
    const int vbase = (blockIdx.x & 1) * 32;
    const int tid = threadIdx.x;
    const int wrp = tid >> 5, l = tid & 31;
    const int k0 = wrp * 8;
    const int vloc = l;
    const int vglob = vbase + vloc;

    const size_t hbase = ((size_t)h) << 12;

    // init Scur[v][k] = S0[h][k][vglob]
    for (int idx = tid; idx < 2048; idx += 256) {
        int k = idx >> 5, v = idx & 31;
        sS0[v * SP + k] = S0[hbase + k * 64 + vbase + v];
    }
    // preload G_0 and G_1 as two separate groups
#pragma unroll
    for (int j = 0; j < 4; j++) {
        int seg = tid + j * 256;
        int r = seg >> 4, c4 = (seg & 15) << 2;
        cp_async16(sGb0 + r * SP + c4, g_G + hbase + r * 64 + c4);
    }
    cp_commit();
    {
        const size_t b1 = ((size_t)(1 * 32 + h)) << 12;
#pragma unroll
        for (int j = 0; j < 4; j++) {
            int seg = tid + j * 256;
            int r = seg >> 4, c4 = (seg & 15) << 2;
            cp_async16(sGb1 + r * SP + c4, g_G + b1 + r * 64 + c4);
        }
        cp_commit();
    }
    // H_0 into regs
    float hcur[8];
#pragma unroll
    for (int r = 0; r < 8; r++)
        hcur[r] = g_H[hbase + (k0 + r) * 64 + vglob];

    float* Scur = sS0; float* Snxt = sS1;
    float* Gcur = sGb0; float* Gn1 = sGb1; float* Gn2 = sGb2;

    for (int i = 0; i < NCHUNK; i++) {
        // retire G(i); leave G(i+1) in flight
        if (i + 1 < NCHUNK) cp_wait1(); else cp_wait0();
        __syncthreads();

        // issue G(i+2) into the buffer whose readers are now done
        if (i + 2 < NCHUNK) {
            const size_t b2 = ((size_t)((i + 2) * 32 + h)) << 12;
#pragma unroll
            for (int j = 0; j < 4; j++) {
                int seg = tid + j * 256;
                int r = seg >> 4, c4 = (seg & 15) << 2;
                cp_async16(Gn2 + r * SP + c4, g_G + b2 + r * 64 + c4);
            }
            cp_commit();
        }

        // emit chunk-start state S(i)
        const size_t basei = ((size_t)(i * 32 + h)) << 12;
        for (int idx = tid; idx < 512; idx += 256) {
            int v = idx >> 4, k4 = (idx & 15) << 2;
            *(float4*)(g_ST + basei + (vbase + v) * 64 + k4) =
                *(const float4*)(Scur + v * SP + k4);
        }
        if (i == NCHUNK - 1) break;

        // register-prefetch H(i+1)
        const size_t basen = ((size_t)((i + 1) * 32 + h)) << 12;
        float hpre[8];
#pragma unroll
        for (int r = 0; r < 8; r++)
            hpre[r] = g_H[basen + (k0 + r) * 64 + vglob];

        // Snxt[v][k0..k0+7] = G(i) rows @ Scur col v + H(i)
        unsigned long long acc[8];
#pragma unroll
        for (int j = 0; j < 8; j++) acc[j] = 0ull;
#pragma unroll 4
        for (int d = 0; d < 64; d += 4) {
            ulonglong2 y = *(const ulonglong2*)(Scur + vloc * SP + d);
#pragma unroll
            for (int r = 0; r < 8; r++) {
                ulonglong2 x = *(const ulonglong2*)(Gcur + (k0 + r) * SP + d);
                ffma2(acc[r], x.x, y.x); ffma2(acc[r], x.y, y.y);
            }
        }
        {
            float4 o0, o1;
            o0.x = hsum(acc[0]) + hcur[0]; o0.y = hsum(acc[1]) + hcur[1];
            o0.z = hsum(acc[2]) + hcur[2]; o0.w = hsum(acc[3]) + hcur[3];
            o1.x = hsum(acc[4]) + hcur[4]; o1.y = hsum(acc[5]) + hcur[5];
            o1.z = hsum(acc[6]) + hcur[6]; o1.w = hsum(acc[7]) + hcur[7];
            *(float4*)(Snxt + vloc * SP + k0)     = o0;
            *(float4*)(Snxt + vloc * SP + k0 + 4) = o1;
        }
#pragma unroll
        for (int j = 0; j < 8; j++) hcur[j] = hpre[j];

        // rotate buffers
        float* t1 = Scur; Scur = Snxt; Snxt = t1;
        float* tg = Gcur; Gcur = Gn1; Gn1 = Gn2; Gn2 = tg;
    }
}

// ---------------------------------------------------------------------------
// Kernel 5: O pass (fully parallel). out += Qeff_i @ S_i. 1024 CTAs.
// ---------------------------------------------------------------------------
__global__ __launch_bounds__(256) void opass_kernel(float* __restrict__ out)
{
    __shared__ float sQe[64 * SP];
    __shared__ float sST[64 * SP];

    const int bi = blockIdx.x;
    const int i = bi >> 5;
    const int h = bi & 31;
    const int tid = threadIdx.x;
    const int ty = tid >> 4, tx = tid & 15;
    const int r0 = ty * 4;

    const size_t base = ((size_t)(i * 32 + h)) << 12;
    for (int idx = tid; idx < 1024; idx += 256) {
        int r = idx >> 4, c4 = (idx & 15) << 2;
        float4 q = *(const float4*)(g_Qeff + base + r * 64 + c4);
        sQe[r * SP + c4 + 0] = q.x; sQe[r * SP + c4 + 1] = q.y;
        sQe[r * SP + c4 + 2] = q.z; sQe[r * SP + c4 + 3] = q.w;
        float4 s = *(const float4*)(g_ST + base + r * 64 + c4);
        sST[r * SP + c4 + 0] = s.x; sST[r * SP + c4 + 1] = s.y;
        sST[r * SP + c4 + 2] = s.z; sST[r * SP + c4 + 3] = s.w;
    }
    __syncthreads();

    unsigned long long acc[16];
#pragma unroll
    for (int j = 0; j < 16; j++) acc[j] = 0ull;
    mm64x(sQe, sST, r0, tx, acc);

#pragma unroll
    for (int ri = 0; ri < 4; ri++) {
        int t = r0 + ri;
        float* op = out + (size_t)(i * 64 + t) * 2048 + h * 64;
#pragma unroll
        for (int ci = 0; ci < 4; ci++) {
            int s = tx + 16 * ci;
            op[s] += hsum(acc[ri * 4 + ci]);
        }
    }
}

// ---------------------------------------------------------------------------
extern "C" void kernel_launch(void* const* d_in, const int* in_sizes, int n_in,
                              void* d_out, int out_size)
{
    const float* x    = (const float*)d_in[0];
    const float* cs   = (const float*)d_in[1];
    const float* s0   = (const float*)d_in[2];
    const float* b    = (const float*)d_in[3];
    const float* a    = (const float*)d_in[4];
    const float* w    = (const float*)d_in[5];
    const float* alog = (const float*)d_in[6];
    const float* dtb  = (const float*)d_in[7];

    const int chunk_smem = (6 * 64 * SP + 5 * 64) * sizeof(float);      // ~105.7 KB
    const int state_smem = (3 * 64 * SP + 2 * 32 * SP) * sizeof(float); // ~69.6 KB
    static bool attr_done = false;
    if (!attr_done) {
        cudaFuncSetAttribute(chunk_kernel,
                             cudaFuncAttributeMaxDynamicSharedMemorySize, chunk_smem);
        cudaFuncSetAttribute(state_kernel,
                             cudaFuncAttributeMaxDynamicSharedMemorySize, state_smem);
        attr_done = true;
    }

    conv_kernel<<<dim3(4, T_STEPS / 4), 256>>>(x, cs, w);
    gates_kernel<<<(T_STEPS * HV + 255) / 256, 256>>>(b, a, alog, dtb);
    chunk_kernel<<<NCHUNK * HV, 256, chunk_smem>>>((float*)d_out);
    state_kernel<<<2 * HV, 256, state_smem>>>(s0);
    opass_kernel<<<NCHUNK * HV, 256>>>((float*)d_out);
}

// round 13
// speedup vs baseline: 1.1734x; 1.0948x over previous
#include <cuda_runtime.h>
#include <cstdint>

#define T_STEPS 2048
#define HV 32
#define HKC 16
#define DHEAD 64
#define CONV_DIM_C 4096
#define KEY_DIM_C 1024
#define NCHUNK 32
#define SP 68          // smem row stride (floats), 16B-aligned

// ---- scratch (static __device__, no allocation) ----
__device__ float g_qn[T_STEPS * HKC * DHEAD];
__device__ float g_kn[T_STEPS * HKC * DHEAD];
__device__ float g_v [T_STEPS * HV * DHEAD];
__device__ float g_g   [T_STEPS * HV];
__device__ float g_beta[T_STEPS * HV];
__device__ float g_Qeff[NCHUNK * HV * 4096];
__device__ float g_G   [NCHUNK * HV * 4096];
__device__ float g_H   [NCHUNK * HV * 4096];
__device__ float g_ST  [NCHUNK * HV * 4096];   // chunk-start states, [v][k]

// ---- f32x2 packed FMA helpers ----
__device__ __forceinline__ void ffma2(unsigned long long& acc,
                                      unsigned long long a, unsigned long long b) {
    asm("fma.rn.f32x2 %0, %1, %2, %0;" : "+l"(acc) : "l"(a), "l"(b));
}
__device__ __forceinline__ float hsum(unsigned long long u) {
    float2 f = *reinterpret_cast<float2*>(&u);
    return f.x + f.y;
}

// ---- cp.async helpers ----
__device__ __forceinline__ void cp_async16(void* dst, const void* src) {
    uint32_t d = (uint32_t)__cvta_generic_to_shared(dst);
    asm volatile("cp.async.cg.shared.global [%0], [%1], 16;" :: "r"(d), "l"(src));
}
__device__ __forceinline__ void cp_commit() {
    asm volatile("cp.async.commit_group;");
}
__device__ __forceinline__ void cp_wait0() {
    asm volatile("cp.async.wait_group 0;");
}
__device__ __forceinline__ void cp_wait1() {
    asm volatile("cp.async.wait_group 1;");
}

// Single-X matmul: Z[r][c] = sum_d X[r][d]*YT[c][d]
__device__ __forceinline__ void mm64x(const float* __restrict__ X,
                                      const float* __restrict__ YT,
                                      int r0, int tx, unsigned long long* __restrict__ acc)
{
#pragma unroll 4
    for (int d = 0; d < 64; d += 4) {
        ulonglong2 x0 = *(const ulonglong2*)(X + (r0 + 0) * SP + d);
        ulonglong2 x1 = *(const ulonglong2*)(X + (r0 + 1) * SP + d);
        ulonglong2 x2 = *(const ulonglong2*)(X + (r0 + 2) * SP + d);
        ulonglong2 x3 = *(const ulonglong2*)(X + (r0 + 3) * SP + d);
        ulonglong2 y0 = *(const ulonglong2*)(YT + (tx +  0) * SP + d);
        ulonglong2 y1 = *(const ulonglong2*)(YT + (tx + 16) * SP + d);
        ulonglong2 y2 = *(const ulonglong2*)(YT + (tx + 32) * SP + d);
        ulonglong2 y3 = *(const ulonglong2*)(YT + (tx + 48) * SP + d);
        ffma2(acc[ 0], x0.x, y0.x); ffma2(acc[ 0], x0.y, y0.y);
        ffma2(acc[ 1], x0.x, y1.x); ffma2(acc[ 1], x0.y, y1.y);
        ffma2(acc[ 2], x0.x, y2.x); ffma2(acc[ 2], x0.y, y2.y);
        ffma2(acc[ 3], x0.x, y3.x); ffma2(acc[ 3], x0.y, y3.y);
        ffma2(acc[ 4], x1.x, y0.x); ffma2(acc[ 4], x1.y, y0.y);
        ffma2(acc[ 5], x1.x, y1.x); ffma2(acc[ 5], x1.y, y1.y);
        ffma2(acc[ 6], x1.x, y2.x); ffma2(acc[ 6], x1.y, y2.y);
        ffma2(acc[ 7], x1.x, y3.x); ffma2(acc[ 7], x1.y, y3.y);
        ffma2(acc[ 8], x2.x, y0.x); ffma2(acc[ 8], x2.y, y0.y);
        ffma2(acc[ 9], x2.x, y1.x); ffma2(acc[ 9], x2.y, y1.y);
        ffma2(acc[10], x2.x, y2.x); ffma2(acc[10], x2.y, y2.y);
        ffma2(acc[11], x2.x, y3.x); ffma2(acc[11], x2.y, y3.y);
        ffma2(acc[12], x3.x, y0.x); ffma2(acc[12], x3.y, y0.y);
        ffma2(acc[13], x3.x, y1.x); ffma2(acc[13], x3.y, y1.y);
        ffma2(acc[14], x3.x, y2.x); ffma2(acc[14], x3.y, y2.y);
        ffma2(acc[15], x3.x, y3.x); ffma2(acc[15], x3.y, y3.y);
    }
}

// Dual-X matmul sharing Y loads (pass A): Z1 = X1@Y, Z2 = X2@Y.
__device__ __forceinline__ void mm64d(const float* __restrict__ X1,
                                      const float* __restrict__ X2,
                                      const float* __restrict__ YT,
                                      int r0, int tx,
                                      unsigned long long* __restrict__ a1,
                                      unsigned long long* __restrict__ a2)
{
#pragma unroll 2
    for (int d = 0; d < 64; d += 4) {
        ulonglong2 y0 = *(const ulonglong2*)(YT + (tx +  0) * SP + d);
        ulonglong2 y1 = *(const ulonglong2*)(YT + (tx + 16) * SP + d);
        ulonglong2 y2 = *(const ulonglong2*)(YT + (tx + 32) * SP + d);
        ulonglong2 y3 = *(const ulonglong2*)(YT + (tx + 48) * SP + d);
#pragma unroll
        for (int r = 0; r < 4; r++) {
            ulonglong2 x = *(const ulonglong2*)(X1 + (r0 + r) * SP + d);
            ffma2(a1[4*r + 0], x.x, y0.x); ffma2(a1[4*r + 0], x.y, y0.y);
            ffma2(a1[4*r + 1], x.x, y1.x); ffma2(a1[4*r + 1], x.y, y1.y);
            ffma2(a1[4*r + 2], x.x, y2.x); ffma2(a1[4*r + 2], x.y, y2.y);
            ffma2(a1[4*r + 3], x.x, y3.x); ffma2(a1[4*r + 3], x.y, y3.y);
        }
#pragma unroll
        for (int r = 0; r < 4; r++) {
            ulonglong2 x = *(const ulonglong2*)(X2 + (r0 + r) * SP + d);
            ffma2(a2[4*r + 0], x.x, y0.x); ffma2(a2[4*r + 0], x.y, y0.y);
            ffma2(a2[4*r + 1], x.x, y1.x); ffma2(a2[4*r + 1], x.y, y1.y);
            ffma2(a2[4*r + 2], x.x, y2.x); ffma2(a2[4*r + 2], x.y, y2.y);
            ffma2(a2[4*r + 3], x.x, y3.x); ffma2(a2[4*r + 3], x.y, y3.y);
        }
    }
}

// ---------------------------------------------------------------------------
// Kernel 1: conv1d(W=4)+silu+split+l2norm. 4 time-rows per CTA.
// ---------------------------------------------------------------------------
__global__ __launch_bounds__(256) void conv_kernel(
    const float* __restrict__ x,
    const float* __restrict__ cstate,
    const float* __restrict__ wgt)
{
    const int t0 = blockIdx.y * 4;
    const int c  = blockIdx.x * 1024 + threadIdx.x * 4;

    float4 w[4];
#pragma unroll
    for (int j = 0; j < 4; j++) w[j] = *(const float4*)(wgt + (size_t)(c + j) * 4);

    float4 xr[7];
#pragma unroll
    for (int rr = 0; rr < 7; rr++) {
        int r = t0 - 3 + rr;
        xr[rr] = (r >= 0) ? *(const float4*)(x + (size_t)r * CONV_DIM_C + c)
                          : *(const float4*)(cstate + (size_t)(r + 3) * CONV_DIM_C + c);
    }

    float acc[4][4];
#pragma unroll
    for (int tt = 0; tt < 4; tt++) {
        float xv0[4] = {xr[tt].x, xr[tt].y, xr[tt].z, xr[tt].w};
        float xv1[4] = {xr[tt+1].x, xr[tt+1].y, xr[tt+1].z, xr[tt+1].w};
        float xv2[4] = {xr[tt+2].x, xr[tt+2].y, xr[tt+2].z, xr[tt+2].w};
        float xv3[4] = {xr[tt+3].x, xr[tt+3].y, xr[tt+3].z, xr[tt+3].w};
#pragma unroll
        for (int j = 0; j < 4; j++) {
            float s = xv0[j] * w[j].x;
            s = fmaf(xv1[j], w[j].y, s);
            s = fmaf(xv2[j], w[j].z, s);
            s = fmaf(xv3[j], w[j].w, s);
            acc[tt][j] = s / (1.f + __expf(-s));
        }
    }

    if (c < 2 * KEY_DIM_C) {
        float ss[4];
#pragma unroll
        for (int tt = 0; tt < 4; tt++) {
            float s = 0.f;
#pragma unroll
            for (int j = 0; j < 4; j++) s = fmaf(acc[tt][j], acc[tt][j], s);
            s += __shfl_xor_sync(0xffffffffu, s, 1);
            s += __shfl_xor_sync(0xffffffffu, s, 2);
            s += __shfl_xor_sync(0xffffffffu, s, 4);
            s += __shfl_xor_sync(0xffffffffu, s, 8);
            ss[tt] = rsqrtf(s + 1e-6f);
        }
        const bool isq = (c < KEY_DIM_C);
#pragma unroll
        for (int tt = 0; tt < 4; tt++) {
            float sc = isq ? ss[tt] * 0.125f : ss[tt];
            float* dst = isq ? (g_qn + (size_t)(t0 + tt) * 1024 + c)
                             : (g_kn + (size_t)(t0 + tt) * 1024 + (c - KEY_DIM_C));
            *(float4*)dst = make_float4(acc[tt][0]*sc, acc[tt][1]*sc, acc[tt][2]*sc, acc[tt][3]*sc);
        }
    } else {
#pragma unroll
        for (int tt = 0; tt < 4; tt++) {
            float* dst = g_v + (size_t)(t0 + tt) * 2048 + (c - 2048);
            *(float4*)dst = make_float4(acc[tt][0], acc[tt][1], acc[tt][2], acc[tt][3]);
        }
    }
}

// ---------------------------------------------------------------------------
// Kernel 2: gates
// ---------------------------------------------------------------------------
__global__ void gates_kernel(
    const float* __restrict__ b, const float* __restrict__ a,
    const float* __restrict__ alog, const float* __restrict__ dtb)
{
    int i = blockIdx.x * blockDim.x + threadIdx.x;
    if (i >= T_STEPS * HV) return;
    int h = i & 31;
    g_beta[i] = 1.f / (1.f + expf(-b[i]));
    float xx = a[i] + dtb[h];
    float sp = (xx > 20.f) ? xx : log1pf(expf(xx));
    g_g[i] = -expf(alog[h]) * sp;
}

// ---------------------------------------------------------------------------
// Kernel 3: per-chunk WY-form precompute (R9 proven). 1024 CTAs, 256 thr.
// ---------------------------------------------------------------------------
__global__ __launch_bounds__(256, 2) void chunk_kernel(float* __restrict__ out)
{
    extern __shared__ float sm[];
    float* sK   = sm;                 // [64][SP] K row-major, then Attn
    float* sKT  = sK  + 64 * SP;      // [64][SP] K^T (later Cbar^T)
    float* sQr  = sKT + 64 * SP;      // [64][SP] q normalized+scaled
    float* sM   = sQr + 64 * SP;      // [64][SP] M (solve matrix) -> W^T
    float* sW   = sM  + 64 * SP;      // [64][SP] W rhs/solved [t][k] -> P^T
    float* sP   = sW  + 64 * SP;      // [64][SP] beta*V / P [t][v]
    float* scg  = sP  + 64 * SP;      // [64]
    float* sE   = scg  + 64;
    float* sBeta= sE   + 64;
    float* sBE  = sBeta+ 64;
    float* sTmp = sBE  + 64;

    const int cid = blockIdx.x;
    const int i = cid >> 5;
    const int h = cid & 31;
    const int tid = threadIdx.x;
    const int ty = tid >> 4, tx = tid & 15;
    const int r0 = ty * 4;

    // ---- load K (+transpose), Q, V (row-major) ----
    const float* Kg = g_kn + (size_t)(i * 64) * 1024 + (h >> 1) * 64;
    const float* Qg = g_qn + (size_t)(i * 64) * 1024 + (h >> 1) * 64;
    const float* Vg = g_v  + (size_t)(i * 64) * 2048 + h * 64;
    for (int idx = tid; idx < 64 * 16; idx += 256) {
        int r = idx >> 4, c4 = (idx & 15) << 2;
        float4 kv = *(const float4*)(Kg + (size_t)r * 1024 + c4);
        sK[r * SP + c4 + 0] = kv.x; sK[r * SP + c4 + 1] = kv.y;
        sK[r * SP + c4 + 2] = kv.z; sK[r * SP + c4 + 3] = kv.w;
        sKT[(c4 + 0) * SP + r] = kv.x; sKT[(c4 + 1) * SP + r] = kv.y;
        sKT[(c4 + 2) * SP + r] = kv.z; sKT[(c4 + 3) * SP + r] = kv.w;
        float4 qv = *(const float4*)(Qg + (size_t)r * 1024 + c4);
        sQr[r * SP + c4 + 0] = qv.x; sQr[r * SP + c4 + 1] = qv.y;
        sQr[r * SP + c4 + 2] = qv.z; sQr[r * SP + c4 + 3] = qv.w;
        float4 vv = *(const float4*)(Vg + (size_t)r * 2048 + c4);
        *(float4*)(sP + r * SP + c4) = vv;
    }
    if (tid < 64) {
        scg[tid]   = g_g   [(size_t)(i * 64 + tid) * 32 + h];
        sBeta[tid] = g_beta[(size_t)(i * 64 + tid) * 32 + h];
    }
    __syncthreads();

    // ---- inclusive scan of log-decay ----
#pragma unroll
    for (int off = 1; off < 64; off <<= 1) {
        float v = 0.f;
        if (tid < 64) v = scg[tid] + ((tid >= off) ? scg[tid - off] : 0.f);
        __syncthreads();
        if (tid < 64) scg[tid] = v;
        __syncthreads();
    }
    if (tid < 64) {
        float e = __expf(scg[tid]);
        sE[tid] = e;
        sBE[tid] = e * sBeta[tid];
        sTmp[tid] = __expf(scg[63] - scg[tid]);
    }
    __syncthreads();

    // ---- RHS init (row-major): sW[t][k] = BE[t]*K[t][k]; sP[t][v] *= beta[t]
    for (int idx = tid; idx < 1024; idx += 256) {
        int r = idx >> 4, c4 = (idx & 15) << 2;
        float be = sBE[r], bb = sBeta[r];
        float4 kv = *(const float4*)(sK + r * SP + c4);
        *(float4*)(sW + r * SP + c4) =
            make_float4(be * kv.x, be * kv.y, be * kv.z, be * kv.w);
        float4 pv = *(const float4*)(sP + r * SP + c4);
        *(float4*)(sP + r * SP + c4) =
            make_float4(bb * pv.x, bb * pv.y, bb * pv.z, bb * pv.w);
    }

    unsigned long long a1[16], a2[16];

    // ---- pass A: Y=K; X1=K -> M, X2=Q -> Attn ----
#pragma unroll
    for (int j = 0; j < 16; j++) { a1[j] = 0ull; a2[j] = 0ull; }
    mm64d(sK, sQr, sK, r0, tx, a1, a2);
    __syncthreads();   // all reads of sK (and RHS init) done before overwrite
#pragma unroll
    for (int ri = 0; ri < 4; ri++) {
        int t = r0 + ri;
        float bt = sBeta[t], ct = scg[t];
#pragma unroll
        for (int ci = 0; ci < 4; ci++) {
            int s = tx + 16 * ci;
            float esc = __expf(ct - scg[s]);
            sM[t * SP + s] = (s < t) ? bt * hsum(a1[ri * 4 + ci]) * esc : 0.f;
            sK[t * SP + s] = (s <= t) ? hsum(a2[ri * 4 + ci]) * esc : 0.f;   // Attn
        }
    }
    __syncthreads();

    // ---- solve (I+M)X = RHS, row-major layout: X[t][cc], lane-contiguous ----
    if (tid < 128) {
        float* X = (tid < 64) ? sW : sP;
        const int cc = tid & 63;
        for (int t = 0; t < 64; t++) {
            float r = X[t * SP + cc];
            const float* Mr = sM + t * SP;
            float b0 = 0.f, b1 = 0.f, b2 = 0.f, b3 = 0.f;
            int s = 0;
            for (; s + 4 <= t; s += 4) {
                b0 = fmaf(Mr[s + 0], X[(s + 0) * SP + cc], b0);
                b1 = fmaf(Mr[s + 1], X[(s + 1) * SP + cc], b1);
                b2 = fmaf(Mr[s + 2], X[(s + 2) * SP + cc], b2);
                b3 = fmaf(Mr[s + 3], X[(s + 3) * SP + cc], b3);
            }
            for (; s < t; s++) b0 = fmaf(Mr[s], X[s * SP + cc], b0);
            X[t * SP + cc] = r - ((b0 + b1) + (b2 + b3));
        }
    }
    __syncthreads();

    // ---- transpose W: sW[t][k] -> sM[k][t]; scale sKT -> Cbar^T ----
    for (int idx = tid; idx < 1024; idx += 256) {
        int r = idx >> 4, c4 = (idx & 15) << 2;
        float4 w = *(const float4*)(sW + r * SP + c4);
        sM[(c4 + 0) * SP + r] = w.x; sM[(c4 + 1) * SP + r] = w.y;
        sM[(c4 + 2) * SP + r] = w.z; sM[(c4 + 3) * SP + r] = w.w;
    }
    for (int idx = tid; idx < 4096; idx += 256) {
        int r = idx >> 6, s = idx & 63;
        sKT[r * SP + s] *= sTmp[s];
    }
    __syncthreads();

    // ---- transpose P: sP[t][v] -> sW[v][t] ----
    for (int idx = tid; idx < 1024; idx += 256) {
        int r = idx >> 4, c4 = (idx & 15) << 2;
        float4 p = *(const float4*)(sP + r * SP + c4);
        sW[(c4 + 0) * SP + r] = p.x; sW[(c4 + 1) * SP + r] = p.y;
        sW[(c4 + 2) * SP + r] = p.z; sW[(c4 + 3) * SP + r] = p.w;
    }
    __syncthreads();

    const size_t base = ((size_t)(i * 32 + h)) << 12;

    // ---- pass B: Y=W^T (sM); X1=Attn -> Qeff, X2=Cbar^T -> G ----
#pragma unroll
    for (int j = 0; j < 16; j++) { a1[j] = 0ull; a2[j] = 0ull; }
    mm64d(sK, sKT, sM, r0, tx, a1, a2);
    {
        float b63 = sE[63];
#pragma unroll
        for (int ri = 0; ri < 4; ri++) {
            int t = r0 + ri;
            float et = sE[t];
#pragma unroll
            for (int ci = 0; ci < 4; ci++) {
                int s = tx + 16 * ci;
                g_Qeff[base + t * 64 + s] = fmaf(et, sQr[t * SP + s], -hsum(a1[ri * 4 + ci]));
                g_G   [base + t * 64 + s] = ((t == s) ? b63 : 0.f) - hsum(a2[ri * 4 + ci]);
            }
        }
    }

    // ---- pass C: Y=P^T (sW); X1=Attn -> Ointra, X2=Cbar^T -> H ----
#pragma unroll
    for (int j = 0; j < 16; j++) { a1[j] = 0ull; a2[j] = 0ull; }
    mm64d(sK, sKT, sW, r0, tx, a1, a2);
#pragma unroll
    for (int ri = 0; ri < 4; ri++) {
        int t = r0 + ri;
        float* op = out + (size_t)(i * 64 + t) * 2048 + h * 64;
#pragma unroll
        for (int ci = 0; ci < 4; ci++) {
            int s = tx + 16 * ci;
            op[s] = hsum(a1[ri * 4 + ci]);
            g_H[base + t * 64 + s] = hsum(a2[ri * 4 + ci]);
        }
    }
}

// ---------------------------------------------------------------------------
// Kernel 4: state pass — 128 CTAs = (head, v-quarter) x 256 threads.
// Lane = (vloc 0..15, d-half 0..1); per-lane 32-element d-half dot, one
// shfl_xor(16) combine. Depth-2 cp.async G pipeline (3 buffers).
// ---------------------------------------------------------------------------
__global__ __launch_bounds__(256) void state_kernel(const float* __restrict__ S0)
{
    extern __shared__ float sms[];
    float* sGb0 = sms;                  // [64][SP] x3 rotating G buffers
    float* sGb1 = sGb0 + 64 * SP;
    float* sGb2 = sGb1 + 64 * SP;
    float* sS0  = sGb2 + 64 * SP;       // [16 v][SP] (k contiguous)
    float* sS1  = sS0  + 16 * SP;

    const int h = blockIdx.x >> 2;
    const int vbase = (blockIdx.x & 3) * 16;
    const int tid = threadIdx.x;
    const int wrp = tid >> 5, l = tid & 31;
    const int k0 = wrp * 8;
    const int vloc = l & 15;
    const int dbase = (l >> 4) * 32;    // d-half
    const int vglob = vbase + vloc;

    const size_t hbase = ((size_t)h) << 12;

    // init Scur[v][k] = S0[h][k][vglob]
    for (int idx = tid; idx < 1024; idx += 256) {
        int k = idx >> 4, v = idx & 15;
        sS0[v * SP + k] = S0[hbase + k * 64 + vbase + v];
    }
    // preload G_0 and G_1 as two separate groups
#pragma unroll
    for (int j = 0; j < 4; j++) {
        int seg = tid + j * 256;
        int r = seg >> 4, c4 = (seg & 15) << 2;
        cp_async16(sGb0 + r * SP + c4, g_G + hbase + r * 64 + c4);
    }
    cp_commit();
    {
        const size_t b1 = ((size_t)(1 * 32 + h)) << 12;
#pragma unroll
        for (int j = 0; j < 4; j++) {
            int seg = tid + j * 256;
            int r = seg >> 4, c4 = (seg & 15) << 2;
            cp_async16(sGb1 + r * SP + c4, g_G + b1 + r * 64 + c4);
        }
        cp_commit();
    }
    // H_0 into regs (lane's v column; duplicated across d-halves, harmless)
    float hcur[8];
#pragma unroll
    for (int r = 0; r < 8; r++)
        hcur[r] = g_H[hbase + (k0 + r) * 64 + vglob];

    float* Scur = sS0; float* Snxt = sS1;
    float* Gcur = sGb0; float* Gn1 = sGb1; float* Gn2 = sGb2;

    for (int i = 0; i < NCHUNK; i++) {
        // retire G(i); leave G(i+1) in flight
        if (i + 1 < NCHUNK) cp_wait1(); else cp_wait0();
        __syncthreads();

        // issue G(i+2) into the buffer whose readers finished before the barrier
        if (i + 2 < NCHUNK) {
            const size_t b2 = ((size_t)((i + 2) * 32 + h)) << 12;
#pragma unroll
            for (int j = 0; j < 4; j++) {
                int seg = tid + j * 256;
                int r = seg >> 4, c4 = (seg & 15) << 2;
                cp_async16(Gn2 + r * SP + c4, g_G + b2 + r * 64 + c4);
            }
            cp_commit();
        }

        // emit chunk-start state S(i): 16 v rows x 64 k = 256 float4s
        const size_t basei = ((size_t)(i * 32 + h)) << 12;
        {
            int v = tid >> 4, k4 = (tid & 15) << 2;
            *(float4*)(g_ST + basei + (vbase + v) * 64 + k4) =
                *(const float4*)(Scur + v * SP + k4);
        }
        if (i == NCHUNK - 1) break;

        // register-prefetch H(i+1)
        const size_t basen = ((size_t)((i + 1) * 32 + h)) << 12;
        float hpre[8];
#pragma unroll
        for (int r = 0; r < 8; r++)
            hpre[r] = g_H[basen + (k0 + r) * 64 + vglob];

        // partial dot over this lane's d-half
        unsigned long long acc[8];
#pragma unroll
        for (int j = 0; j < 8; j++) acc[j] = 0ull;
#pragma unroll 4
        for (int dd = 0; dd < 32; dd += 4) {
            const int d = dbase + dd;
            ulonglong2 y = *(const ulonglong2*)(Scur + vloc * SP + d);
#pragma unroll
            for (int r = 0; r < 8; r++) {
                ulonglong2 x = *(const ulonglong2*)(Gcur + (k0 + r) * SP + d);
                ffma2(acc[r], x.x, y.x); ffma2(acc[r], x.y, y.y);
            }
        }
        // combine d-halves across lane pairs (l, l^16)
        float sfull[8];
#pragma unroll
        for (int r = 0; r < 8; r++) {
            float s = hsum(acc[r]);
            s += __shfl_xor_sync(0xffffffffu, s, 16);
            sfull[r] = s + hcur[r];
        }
        if (l < 16) {
            float4 o0 = make_float4(sfull[0], sfull[1], sfull[2], sfull[3]);
            float4 o1 = make_float4(sfull[4], sfull[5], sfull[6], sfull[7]);
            *(float4*)(Snxt + vloc * SP + k0)     = o0;
            *(float4*)(Snxt + vloc * SP + k0 + 4) = o1;
        }
#pragma unroll
        for (int j = 0; j < 8; j++) hcur[j] = hpre[j];

        // rotate buffers
        float* t1 = Scur; Scur = Snxt; Snxt = t1;
        float* tg = Gcur; Gcur = Gn1; Gn1 = Gn2; Gn2 = tg;
    }
}

// ---------------------------------------------------------------------------
// Kernel 5: O pass (fully parallel). out += Qeff_i @ S_i. 1024 CTAs.
// ---------------------------------------------------------------------------
__global__ __launch_bounds__(256) void opass_kernel(float* __restrict__ out)
{
    __shared__ float sQe[64 * SP];
    __shared__ float sST[64 * SP];

    const int bi = blockIdx.x;
    const int i = bi >> 5;
    const int h = bi & 31;
    const int tid = threadIdx.x;
    const int ty = tid >> 4, tx = tid & 15;
    const int r0 = ty * 4;

    const size_t base = ((size_t)(i * 32 + h)) << 12;
    for (int idx = tid; idx < 1024; idx += 256) {
        int r = idx >> 4, c4 = (idx & 15) << 2;
        float4 q = *(const float4*)(g_Qeff + base + r * 64 + c4);
        sQe[r * SP + c4 + 0] = q.x; sQe[r * SP + c4 + 1] = q.y;
        sQe[r * SP + c4 + 2] = q.z; sQe[r * SP + c4 + 3] = q.w;
        float4 s = *(const float4*)(g_ST + base + r * 64 + c4);
        sST[r * SP + c4 + 0] = s.x; sST[r * SP + c4 + 1] = s.y;
        sST[r * SP + c4 + 2] = s.z; sST[r * SP + c4 + 3] = s.w;
    }
    __syncthreads();

    unsigned long long acc[16];
#pragma unroll
    for (int j = 0; j < 16; j++) acc[j] = 0ull;
    mm64x(sQe, sST, r0, tx, acc);

#pragma unroll
    for (int ri = 0; ri < 4; ri++) {
        int t = r0 + ri;
        float* op = out + (size_t)(i * 64 + t) * 2048 + h * 64;
#pragma unroll
        for (int ci = 0; ci < 4; ci++) {
            int s = tx + 16 * ci;
            op[s] += hsum(acc[ri * 4 + ci]);
        }
    }
}

// ---------------------------------------------------------------------------
extern "C" void kernel_launch(void* const* d_in, const int* in_sizes, int n_in,
                              void* d_out, int out_size)
{
    const float* x    = (const float*)d_in[0];
    const float* cs   = (const float*)d_in[1];
    const float* s0   = (const float*)d_in[2];
    const float* b    = (const float*)d_in[3];
    const float* a    = (const float*)d_in[4];
    const float* w    = (const float*)d_in[5];
    const float* alog = (const float*)d_in[6];
    const float* dtb  = (const float*)d_in[7];

    const int chunk_smem = (6 * 64 * SP + 5 * 64) * sizeof(float);      // ~105.7 KB
    const int state_smem = (3 * 64 * SP + 2 * 16 * SP) * sizeof(float); // ~59.5 KB
    static bool attr_done = false;
    if (!attr_done) {
        cudaFuncSetAttribute(chunk_kernel,
                             cudaFuncAttributeMaxDynamicSharedMemorySize, chunk_smem);
        cudaFuncSetAttribute(state_kernel,
                             cudaFuncAttributeMaxDynamicSharedMemorySize, state_smem);
        attr_done = true;
    }

    conv_kernel<<<dim3(4, T_STEPS / 4), 256>>>(x, cs, w);
    gates_kernel<<<(T_STEPS * HV + 255) / 256, 256>>>(b, a, alog, dtb);
    chunk_kernel<<<NCHUNK * HV, 256, chunk_smem>>>((float*)d_out);
    state_kernel<<<4 * HV, 256, state_smem>>>(s0);
    opass_kernel<<<NCHUNK * HV, 256>>>((float*)d_out);
}